// round 7
// baseline (speedup 1.0000x reference)
#include <cuda_runtime.h>
#include <cuda_bf16.h>
#include <cstdint>
#include <cstddef>

#define NNODES   10000
#define NEDGES   160000
#define NETOT    170000   // + self loops
#define HMAX     8

// ---------------- scratch (device globals; no allocation allowed) ----------
__device__ float g_hx [NNODES * 512];   // W-transformed features of current layer
__device__ float g_f1 [NNODES * 512];   // layer0 output
__device__ float g_f2 [NNODES * 512];   // layer1 output
__device__ float g_als[NNODES * HMAX];
__device__ float g_ald[NNODES * HMAX];
__device__ int   g_deg[NNODES];
__device__ int   g_off[NNODES + 1];
__device__ int   g_cur[NNODES];
__device__ int   g_csr_src[NETOT];

// bf16 split buffers
__device__ __nv_bfloat16 g_ahi[NNODES * 512];
__device__ __nv_bfloat16 g_alo[NNODES * 512];
__device__ __nv_bfloat16 g_w0hi[256 * 512], g_w0lo[256 * 512];
__device__ __nv_bfloat16 g_w1hi[512 * 512], g_w1lo[512 * 512];
__device__ __nv_bfloat16 g_w2hi[512 * 64],  g_w2lo[512 * 64];   // 512*40 used

// ---------------- CSR build ------------------------------------------------
__global__ void zero_deg_kernel() {
    int i = blockIdx.x * blockDim.x + threadIdx.x;
    if (i < NNODES) g_deg[i] = 0;
}

__global__ void count_kernel(const int* __restrict__ ei) {
    int i = blockIdx.x * blockDim.x + threadIdx.x;
    if (i >= NETOT) return;
    int dst = (i < NEDGES) ? ei[NEDGES + i] : (i - NEDGES);
    atomicAdd(&g_deg[dst], 1);
}

__global__ void scan_kernel() {
    __shared__ int sm[1024];
    int tid = threadIdx.x;
    const int SEG = (NNODES + 1023) / 1024;   // 10
    int beg = tid * SEG;
    int end = beg + SEG; if (end > NNODES) end = NNODES;
    int s = 0;
    for (int i = beg; i < end; i++) s += g_deg[i];
    sm[tid] = s;
    __syncthreads();
    for (int d = 1; d < 1024; d <<= 1) {
        int v = (tid >= d) ? sm[tid - d] : 0;
        __syncthreads();
        sm[tid] += v;
        __syncthreads();
    }
    int run = (tid > 0) ? sm[tid - 1] : 0;
    for (int i = beg; i < end; i++) {
        g_off[i] = run;
        g_cur[i] = run;
        run += g_deg[i];
    }
    if (tid == 1023) g_off[NNODES] = sm[1023];
}

__global__ void scatter_kernel(const int* __restrict__ ei) {
    int i = blockIdx.x * blockDim.x + threadIdx.x;
    if (i >= NETOT) return;
    int src, dst;
    if (i < NEDGES) { src = ei[i]; dst = ei[NEDGES + i]; }
    else            { src = i - NEDGES; dst = src; }
    int p = atomicAdd(&g_cur[dst], 1);
    g_csr_src[p] = src;
}

// ---------------- fp32 -> (bf16 hi, bf16 lo) split --------------------------
__global__ void split_kernel(const float* __restrict__ in,
                             __nv_bfloat16* __restrict__ hi,
                             __nv_bfloat16* __restrict__ lo, int n)
{
    int i = blockIdx.x * blockDim.x + threadIdx.x;
    if (i >= n) return;
    float x = in[i];
    __nv_bfloat16 h = __float2bfloat16_rn(x);
    float r = x - __bfloat162float(h);
    hi[i] = h;
    lo[i] = __float2bfloat16_rn(r);
}

// ---------------- tensor-core GEMM (split bf16, 3 passes) -------------------
// C[M,N] = Ahi@Bhi + Ahi@Blo + Alo@Bhi   (all fp32 accumulate)
// A: [M,K] bf16 row-major; B: [K,N] bf16 row-major; C fp32 row-major.
// Block tile 128x128, BK=32, 8 warps (4x2), warp tile 32x64, mma m16n8k16.
#define RS 40   // smem row stride in bf16 (conflict-free fragment loads)

__device__ __forceinline__ void mma16816(float* c, const uint32_t* a, const uint32_t* b)
{
    asm volatile(
        "mma.sync.aligned.m16n8k16.row.col.f32.bf16.bf16.f32 "
        "{%0,%1,%2,%3}, {%4,%5,%6,%7}, {%8,%9}, {%0,%1,%2,%3};\n"
        : "+f"(c[0]), "+f"(c[1]), "+f"(c[2]), "+f"(c[3])
        : "r"(a[0]), "r"(a[1]), "r"(a[2]), "r"(a[3]), "r"(b[0]), "r"(b[1]));
}

__global__ __launch_bounds__(256) void gemm_mma_kernel(
    const __nv_bfloat16* __restrict__ Ahi, const __nv_bfloat16* __restrict__ Alo,
    const __nv_bfloat16* __restrict__ Bhi, const __nv_bfloat16* __restrict__ Blo,
    float* __restrict__ C, int M, int K, int Ncol)
{
    __shared__ __align__(16) __nv_bfloat16 As[128 * RS];
    __shared__ __align__(16) __nv_bfloat16 Bs[128 * RS];

    int tid  = threadIdx.x;
    int wid  = tid >> 5;
    int lane = tid & 31;
    int g    = lane >> 2;          // 0..7
    int tig  = lane & 3;           // 0..3
    int wm   = wid & 3;            // 0..3  (M dir)
    int wn   = wid >> 2;           // 0..1  (N dir)
    int wrow = wm * 32;
    int wcol = wn * 64;
    int row0 = blockIdx.x * 128;
    int col0 = blockIdx.y * 128;

    float acc[2][8][4];
#pragma unroll
    for (int i = 0; i < 2; i++)
#pragma unroll
        for (int j = 0; j < 8; j++)
#pragma unroll
            for (int q = 0; q < 4; q++) acc[i][j][q] = 0.f;

#pragma unroll 1
    for (int pass = 0; pass < 3; pass++) {
        const __nv_bfloat16* A = (pass < 2) ? Ahi : Alo;
        const __nv_bfloat16* B = (pass == 1) ? Blo : Bhi;

#pragma unroll 1
        for (int k0 = 0; k0 < K; k0 += 32) {
            // ---- load A tile [128 x 32] (4 bf16 per chunk, 4 chunks/thread)
#pragma unroll
            for (int i = 0; i < 4; i++) {
                int e   = tid + i * 256;      // chunk id 0..1023
                int row = e >> 3;             // 8 chunks per row
                int col = (e & 7) * 4;
                uint2 v = make_uint2(0u, 0u);
                int gr = row0 + row;
                if (gr < M)
                    v = *(const uint2*)(A + (size_t)gr * K + k0 + col);
                *(uint2*)&As[row * RS + col] = v;
            }
            // ---- load B tile [32 x 128], store transposed Bs[n][k]
#pragma unroll
            for (int i = 0; i < 4; i++) {
                int e  = tid + i * 256;
                int kk = e >> 5;              // 0..31
                int nn = (e & 31) * 4;        // 0..124
                __nv_bfloat16 tmp[4];
                if (col0 + nn < Ncol) {
                    *(uint2*)tmp = *(const uint2*)(B + (size_t)(k0 + kk) * Ncol + col0 + nn);
                } else {
                    tmp[0] = tmp[1] = tmp[2] = tmp[3] = __nv_bfloat16(0.f);
                }
#pragma unroll
                for (int j = 0; j < 4; j++)
                    Bs[(nn + j) * RS + kk] = tmp[j];
            }
            __syncthreads();

#pragma unroll
            for (int kk16 = 0; kk16 < 2; kk16++) {
                int kb = kk16 * 16 + tig * 2;
                uint32_t afr[2][4];
#pragma unroll
                for (int ma = 0; ma < 2; ma++) {
                    int r = wrow + ma * 16 + g;
                    const uint32_t* p0 = (const uint32_t*)&As[r * RS + kb];
                    const uint32_t* p1 = (const uint32_t*)&As[(r + 8) * RS + kb];
                    afr[ma][0] = p0[0];
                    afr[ma][1] = p1[0];
                    afr[ma][2] = p0[4];
                    afr[ma][3] = p1[4];
                }
                uint32_t bfr[8][2];
#pragma unroll
                for (int na = 0; na < 8; na++) {
                    int n = wcol + na * 8 + g;
                    const uint32_t* p = (const uint32_t*)&Bs[n * RS + kb];
                    bfr[na][0] = p[0];
                    bfr[na][1] = p[4];
                }
#pragma unroll
                for (int ma = 0; ma < 2; ma++)
#pragma unroll
                    for (int na = 0; na < 8; na++)
                        mma16816(acc[ma][na], afr[ma], bfr[na]);
            }
            __syncthreads();
        }
    }

    // ---- epilogue
#pragma unroll
    for (int ma = 0; ma < 2; ma++) {
#pragma unroll
        for (int na = 0; na < 8; na++) {
            int r = row0 + wrow + ma * 16 + g;
            int c = col0 + wcol + na * 8 + tig * 2;
            if (c < Ncol) {
                if (r < M)
                    *(float2*)&C[(size_t)r * Ncol + c] =
                        make_float2(acc[ma][na][0], acc[ma][na][1]);
                if (r + 8 < M)
                    *(float2*)&C[(size_t)(r + 8) * Ncol + c] =
                        make_float2(acc[ma][na][2], acc[ma][na][3]);
            }
        }
    }
}

// ---------------- attention logits: al_s/al_d [N,H] ------------------------
__global__ void logits_kernel(const float* __restrict__ hx,
                              const float* __restrict__ a_src,
                              const float* __restrict__ a_dst,
                              float* __restrict__ als, float* __restrict__ ald,
                              int H, int C)
{
    int n = blockIdx.x;
    int warp = threadIdx.x >> 5;
    int lane = threadIdx.x & 31;
    if (warp >= H) return;
    const float* row = hx + (size_t)n * H * C + warp * C;
    float ss = 0.f, sd = 0.f;
    for (int c = lane; c < C; c += 32) {
        float v = row[c];
        ss += v * a_src[warp * C + c];
        sd += v * a_dst[warp * C + c];
    }
#pragma unroll
    for (int s = 16; s > 0; s >>= 1) {
        ss += __shfl_down_sync(0xffffffffu, ss, s);
        sd += __shfl_down_sync(0xffffffffu, sd, s);
    }
    if (lane == 0) {
        als[n * H + warp] = ss;
        ald[n * H + warp] = sd;
    }
}

// ---------------- per-dst softmax + aggregation ----------------------------
__global__ __launch_bounds__(256) void aggregate_kernel(
    const float* __restrict__ hx,
    const float* __restrict__ als, const float* __restrict__ ald,
    const float* __restrict__ bias, float* __restrict__ out,
    int H, int C, int act)
{
    int n   = blockIdx.x;
    int HC  = H * C;
    int tid = threadIdx.x;
    int h   = tid % H;        // H divides 256 (8 or 1)
    int w   = tid / H;
    int NW  = 256 / H;

    __shared__ float sm_ald[HMAX];
    __shared__ float scratch[256];
    __shared__ float sm_alpha[256];
    __shared__ int   sm_src[256];

    int e0  = g_off[n];
    int deg = g_off[n + 1] - e0;

    if (tid < H) sm_ald[tid] = ald[(size_t)n * H + tid];
    __syncthreads();
    float myald = sm_ald[h];

    float mx = -1e30f;
    for (int j = w; j < deg; j += NW) {
        int s = g_csr_src[e0 + j];
        float v = als[(size_t)s * H + h] + myald;
        v = (v >= 0.f) ? v : 0.2f * v;
        mx = fmaxf(mx, v);
    }
    scratch[tid] = mx;
    __syncthreads();
    for (int st = NW >> 1; st > 0; st >>= 1) {
        if (w < st) scratch[tid] = fmaxf(scratch[tid], scratch[tid + st * H]);
        __syncthreads();
    }
    float m = scratch[h];
    __syncthreads();

    float sum = 0.f;
    for (int j = w; j < deg; j += NW) {
        int s = g_csr_src[e0 + j];
        float v = als[(size_t)s * H + h] + myald;
        v = (v >= 0.f) ? v : 0.2f * v;
        sum += expf(v - m);
    }
    scratch[tid] = sum;
    __syncthreads();
    for (int st = NW >> 1; st > 0; st >>= 1) {
        if (w < st) scratch[tid] += scratch[tid + st * H];
        __syncthreads();
    }
    float denom = scratch[h] + 1e-16f;
    __syncthreads();

    float acc0 = 0.f, acc1 = 0.f;
    int c0 = tid, c1 = tid + 256;
    int h0 = (c0 < HC) ? (c0 / C) : 0;
    int h1 = (c1 < HC) ? (c1 / C) : 0;

    for (int base = 0; base < deg; base += NW) {
        int j = base + w;
        if (j < deg) {
            int s = g_csr_src[e0 + j];
            if (h == 0) sm_src[w] = s;
            float v = als[(size_t)s * H + h] + myald;
            v = (v >= 0.f) ? v : 0.2f * v;
            sm_alpha[w * H + h] = expf(v - m) / denom;
        }
        __syncthreads();
        int lim = deg - base; if (lim > NW) lim = NW;
        for (int j2 = 0; j2 < lim; j2++) {
            int s = sm_src[j2];
            const float* hrow = hx + (size_t)s * HC;
            float a0 = sm_alpha[j2 * H + h0];
            float a1 = sm_alpha[j2 * H + h1];
            if (c0 < HC) acc0 += hrow[c0] * a0;
            if (c1 < HC) acc1 += hrow[c1] * a1;
        }
        __syncthreads();
    }

    if (c0 < HC) {
        float o = acc0 + bias[c0];
        if (act) o = (o > 0.f) ? o : expm1f(o);
        out[(size_t)n * HC + c0] = o;
    }
    if (c1 < HC) {
        float o = acc1 + bias[c1];
        if (act) o = (o > 0.f) ? o : expm1f(o);
        out[(size_t)n * HC + c1] = o;
    }
}

// ---------------- host -----------------------------------------------------
extern "C" void kernel_launch(void* const* d_in, const int* in_sizes, int n_in,
                              void* d_out, int out_size)
{
    const float* x      = (const float*)d_in[0];
    const int*   ei     = (const int*)  d_in[1];
    const float* W0     = (const float*)d_in[2];
    const float* a_src0 = (const float*)d_in[3];
    const float* a_dst0 = (const float*)d_in[4];
    const float* b0     = (const float*)d_in[5];
    const float* W1     = (const float*)d_in[6];
    const float* a_src1 = (const float*)d_in[7];
    const float* a_dst1 = (const float*)d_in[8];
    const float* b1     = (const float*)d_in[9];
    const float* W2     = (const float*)d_in[10];
    const float* a_src2 = (const float*)d_in[11];
    const float* a_dst2 = (const float*)d_in[12];
    const float* b2     = (const float*)d_in[13];
    float* out = (float*)d_out;

    float *hx, *f1, *f2, *als, *ald;
    cudaGetSymbolAddress((void**)&hx,  g_hx);
    cudaGetSymbolAddress((void**)&f1,  g_f1);
    cudaGetSymbolAddress((void**)&f2,  g_f2);
    cudaGetSymbolAddress((void**)&als, g_als);
    cudaGetSymbolAddress((void**)&ald, g_ald);
    __nv_bfloat16 *ahi, *alo, *w0hi, *w0lo, *w1hi, *w1lo, *w2hi, *w2lo;
    cudaGetSymbolAddress((void**)&ahi,  g_ahi);
    cudaGetSymbolAddress((void**)&alo,  g_alo);
    cudaGetSymbolAddress((void**)&w0hi, g_w0hi);
    cudaGetSymbolAddress((void**)&w0lo, g_w0lo);
    cudaGetSymbolAddress((void**)&w1hi, g_w1hi);
    cudaGetSymbolAddress((void**)&w1lo, g_w1lo);
    cudaGetSymbolAddress((void**)&w2hi, g_w2hi);
    cudaGetSymbolAddress((void**)&w2lo, g_w2lo);

    // CSR build (by dst)
    zero_deg_kernel<<<(NNODES + 255) / 256, 256>>>();
    count_kernel<<<(NETOT + 255) / 256, 256>>>(ei);
    scan_kernel<<<1, 1024>>>();
    scatter_kernel<<<(NETOT + 255) / 256, 256>>>(ei);

    // weight splits
    split_kernel<<<(256 * 512 + 255) / 256, 256>>>(W0, w0hi, w0lo, 256 * 512);
    split_kernel<<<(512 * 512 + 255) / 256, 256>>>(W1, w1hi, w1lo, 512 * 512);
    split_kernel<<<(512 * 40  + 255) / 256, 256>>>(W2, w2hi, w2lo, 512 * 40);

    // ---- layer 0: 256 -> 8x64, ELU
    {
        split_kernel<<<(NNODES * 256 + 255) / 256, 256>>>(x, ahi, alo, NNODES * 256);
        dim3 grid((NNODES + 127) / 128, 4);
        gemm_mma_kernel<<<grid, 256>>>(ahi, alo, w0hi, w0lo, hx, NNODES, 256, 512);
        logits_kernel<<<NNODES, 256>>>(hx, a_src0, a_dst0, als, ald, 8, 64);
        aggregate_kernel<<<NNODES, 256>>>(hx, als, ald, b0, f1, 8, 64, 1);
    }
    // ---- layer 1: 512 -> 8x64, ELU
    {
        split_kernel<<<(NNODES * 512 + 255) / 256, 256>>>(f1, ahi, alo, NNODES * 512);
        dim3 grid((NNODES + 127) / 128, 4);
        gemm_mma_kernel<<<grid, 256>>>(ahi, alo, w1hi, w1lo, hx, NNODES, 512, 512);
        logits_kernel<<<NNODES, 256>>>(hx, a_src1, a_dst1, als, ald, 8, 64);
        aggregate_kernel<<<NNODES, 256>>>(hx, als, ald, b1, f2, 8, 64, 1);
    }
    // ---- layer 2: 512 -> 1x40, no activation, write d_out
    {
        split_kernel<<<(NNODES * 512 + 255) / 256, 256>>>(f2, ahi, alo, NNODES * 512);
        dim3 grid((NNODES + 127) / 128, 1);
        gemm_mma_kernel<<<grid, 256>>>(ahi, alo, w2hi, w2lo, hx, NNODES, 512, 40);
        logits_kernel<<<NNODES, 32>>>(hx, a_src2, a_dst2, als, ald, 1, 40);
        aggregate_kernel<<<NNODES, 256>>>(hx, als, ald, b2, out, 1, 40, 0);
    }
    (void)in_sizes; (void)n_in; (void)out_size;
}

// round 8
// speedup vs baseline: 1.2696x; 1.2696x over previous
#include <cuda_runtime.h>
#include <cuda_bf16.h>
#include <cstdint>
#include <cstddef>

#define NNODES   10000
#define NEDGES   160000
#define NETOT    170000   // + self loops
#define HMAX     8

// ---------------- scratch (device globals; no allocation allowed) ----------
__device__ float g_hx [NNODES * 512];
__device__ float g_f1 [NNODES * 512];
__device__ float g_f2 [NNODES * 512];
__device__ float g_als[NNODES * HMAX];
__device__ float g_ald[NNODES * HMAX];
__device__ int   g_deg[NNODES];
__device__ int   g_off[NNODES + 1];
__device__ int   g_cur[NNODES];
__device__ int   g_csr_src[NETOT];

// bf16 split weight buffers
__device__ __nv_bfloat16 g_w0hi[256 * 512], g_w0lo[256 * 512];
__device__ __nv_bfloat16 g_w1hi[512 * 512], g_w1lo[512 * 512];
__device__ __nv_bfloat16 g_w2hi[512 * 40],  g_w2lo[512 * 40];

#define W0N (256 * 512)
#define W1N (512 * 512)
#define W2N (512 * 40)

// ---------------- combined weight split (one launch) ------------------------
__global__ void split_weights_kernel(const float* __restrict__ W0,
                                     const float* __restrict__ W1,
                                     const float* __restrict__ W2)
{
    int i = blockIdx.x * blockDim.x + threadIdx.x;
    const float* src;
    __nv_bfloat16 *hi, *lo;
    int j;
    if (i < W0N)                   { src = W0; hi = g_w0hi; lo = g_w0lo; j = i; }
    else if (i < W0N + W1N)        { src = W1; hi = g_w1hi; lo = g_w1lo; j = i - W0N; }
    else if (i < W0N + W1N + W2N)  { src = W2; hi = g_w2hi; lo = g_w2lo; j = i - W0N - W1N; }
    else return;
    float x = src[j];
    __nv_bfloat16 h = __float2bfloat16_rn(x);
    hi[j] = h;
    lo[j] = __float2bfloat16_rn(x - __bfloat162float(h));
}

// ---------------- CSR build ------------------------------------------------
__global__ void zero_deg_kernel() {
    int i = blockIdx.x * blockDim.x + threadIdx.x;
    if (i < NNODES) g_deg[i] = 0;
}

__global__ void count_kernel(const int* __restrict__ ei) {
    int i = blockIdx.x * blockDim.x + threadIdx.x;
    if (i >= NETOT) return;
    int dst = (i < NEDGES) ? ei[NEDGES + i] : (i - NEDGES);
    atomicAdd(&g_deg[dst], 1);
}

__global__ void scan_kernel() {
    __shared__ int sm[1024];
    int tid = threadIdx.x;
    const int SEG = (NNODES + 1023) / 1024;
    int beg = tid * SEG;
    int end = beg + SEG; if (end > NNODES) end = NNODES;
    int s = 0;
    for (int i = beg; i < end; i++) s += g_deg[i];
    sm[tid] = s;
    __syncthreads();
    for (int d = 1; d < 1024; d <<= 1) {
        int v = (tid >= d) ? sm[tid - d] : 0;
        __syncthreads();
        sm[tid] += v;
        __syncthreads();
    }
    int run = (tid > 0) ? sm[tid - 1] : 0;
    for (int i = beg; i < end; i++) {
        g_off[i] = run;
        g_cur[i] = run;
        run += g_deg[i];
    }
    if (tid == 1023) g_off[NNODES] = sm[1023];
}

__global__ void scatter_kernel(const int* __restrict__ ei) {
    int i = blockIdx.x * blockDim.x + threadIdx.x;
    if (i >= NETOT) return;
    int src, dst;
    if (i < NEDGES) { src = ei[i]; dst = ei[NEDGES + i]; }
    else            { src = i - NEDGES; dst = src; }
    int p = atomicAdd(&g_cur[dst], 1);
    g_csr_src[p] = src;
}

// ---------------- tensor-core GEMM, 3 products in ONE k-loop ----------------
// C = Ahi@Bhi + Ahi@Blo + Alo@Bhi   ; A fp32 [M,K] split in-kernel.
// Block tile 128x128, BK=32, 8 warps (4x2), warp tile 32x64, mma m16n8k16.
#define RS 40   // smem row stride in bf16 (conflict-free fragment loads)

__device__ __forceinline__ void mma16816(float* c, const uint32_t* a, const uint32_t* b)
{
    asm volatile(
        "mma.sync.aligned.m16n8k16.row.col.f32.bf16.bf16.f32 "
        "{%0,%1,%2,%3}, {%4,%5,%6,%7}, {%8,%9}, {%0,%1,%2,%3};\n"
        : "+f"(c[0]), "+f"(c[1]), "+f"(c[2]), "+f"(c[3])
        : "r"(a[0]), "r"(a[1]), "r"(a[2]), "r"(a[3]), "r"(b[0]), "r"(b[1]));
}

__global__ __launch_bounds__(256, 2) void gemm_mma3_kernel(
    const float* __restrict__ A,
    const __nv_bfloat16* __restrict__ Bhi, const __nv_bfloat16* __restrict__ Blo,
    float* __restrict__ C, int M, int K, int Ncol)
{
    __shared__ __align__(16) __nv_bfloat16 Ash[128 * RS];
    __shared__ __align__(16) __nv_bfloat16 Asl[128 * RS];
    __shared__ __align__(16) __nv_bfloat16 Bsh[128 * RS];
    __shared__ __align__(16) __nv_bfloat16 Bsl[128 * RS];

    int tid  = threadIdx.x;
    int wid  = tid >> 5;
    int lane = tid & 31;
    int g    = lane >> 2;          // 0..7
    int tig  = lane & 3;           // 0..3
    int wm   = wid & 3;            // M dir
    int wn   = wid >> 2;           // N dir
    int wrow = wm * 32;
    int wcol = wn * 64;
    int row0 = blockIdx.x * 128;
    int col0 = blockIdx.y * 128;

    float acc[2][8][4];
#pragma unroll
    for (int i = 0; i < 2; i++)
#pragma unroll
        for (int j = 0; j < 8; j++)
#pragma unroll
            for (int q = 0; q < 4; q++) acc[i][j][q] = 0.f;

#pragma unroll 1
    for (int k0 = 0; k0 < K; k0 += 32) {
        // ---- A tile [128x32] fp32 -> split to Ash/Asl
#pragma unroll
        for (int i = 0; i < 4; i++) {
            int e   = tid + i * 256;          // 0..1023 float4 chunks
            int row = e >> 3;                 // 8 chunks per row
            int col = (e & 7) * 4;
            float4 v = make_float4(0.f, 0.f, 0.f, 0.f);
            int gr = row0 + row;
            if (gr < M) v = *(const float4*)(A + (size_t)gr * K + k0 + col);
            __nv_bfloat16 h[4], l[4];
            float f[4] = {v.x, v.y, v.z, v.w};
#pragma unroll
            for (int q = 0; q < 4; q++) {
                h[q] = __float2bfloat16_rn(f[q]);
                l[q] = __float2bfloat16_rn(f[q] - __bfloat162float(h[q]));
            }
            *(uint2*)&Ash[row * RS + col] = *(uint2*)h;
            *(uint2*)&Asl[row * RS + col] = *(uint2*)l;
        }
        // ---- B tiles [32x128] -> transposed Bsh/Bsl [n][k]
#pragma unroll
        for (int i = 0; i < 4; i++) {
            int e  = tid + i * 256;
            int kk = e >> 5;                  // 0..31
            int nn = (e & 31) * 4;            // 0..124
            __nv_bfloat16 th[4], tl[4];
            if (col0 + nn < Ncol) {
                size_t off = (size_t)(k0 + kk) * Ncol + col0 + nn;
                *(uint2*)th = *(const uint2*)(Bhi + off);
                *(uint2*)tl = *(const uint2*)(Blo + off);
            } else {
                th[0]=th[1]=th[2]=th[3] = __nv_bfloat16(0.f);
                tl[0]=tl[1]=tl[2]=tl[3] = __nv_bfloat16(0.f);
            }
#pragma unroll
            for (int j = 0; j < 4; j++) {
                Bsh[(nn + j) * RS + kk] = th[j];
                Bsl[(nn + j) * RS + kk] = tl[j];
            }
        }
        __syncthreads();

#pragma unroll
        for (int kk16 = 0; kk16 < 2; kk16++) {
            int kb = kk16 * 16 + tig * 2;
            uint32_t ahi[2][4], alo[2][4];
#pragma unroll
            for (int ma = 0; ma < 2; ma++) {
                int r = wrow + ma * 16 + g;
                const uint32_t* ph0 = (const uint32_t*)&Ash[r * RS + kb];
                const uint32_t* ph1 = (const uint32_t*)&Ash[(r + 8) * RS + kb];
                ahi[ma][0] = ph0[0]; ahi[ma][1] = ph1[0];
                ahi[ma][2] = ph0[4]; ahi[ma][3] = ph1[4];
                const uint32_t* pl0 = (const uint32_t*)&Asl[r * RS + kb];
                const uint32_t* pl1 = (const uint32_t*)&Asl[(r + 8) * RS + kb];
                alo[ma][0] = pl0[0]; alo[ma][1] = pl1[0];
                alo[ma][2] = pl0[4]; alo[ma][3] = pl1[4];
            }
#pragma unroll
            for (int na = 0; na < 8; na++) {
                int n = wcol + na * 8 + g;
                const uint32_t* pb = (const uint32_t*)&Bsh[n * RS + kb];
                uint32_t bh[2] = { pb[0], pb[4] };
                const uint32_t* pl = (const uint32_t*)&Bsl[n * RS + kb];
                uint32_t bl[2] = { pl[0], pl[4] };
#pragma unroll
                for (int ma = 0; ma < 2; ma++) {
                    mma16816(acc[ma][na], ahi[ma], bh);
                    mma16816(acc[ma][na], ahi[ma], bl);
                    mma16816(acc[ma][na], alo[ma], bh);
                }
            }
        }
        __syncthreads();
    }

    // ---- epilogue
#pragma unroll
    for (int ma = 0; ma < 2; ma++) {
#pragma unroll
        for (int na = 0; na < 8; na++) {
            int r = row0 + wrow + ma * 16 + g;
            int c = col0 + wcol + na * 8 + tig * 2;
            if (c < Ncol) {
                if (r < M)
                    *(float2*)&C[(size_t)r * Ncol + c] =
                        make_float2(acc[ma][na][0], acc[ma][na][1]);
                if (r + 8 < M)
                    *(float2*)&C[(size_t)(r + 8) * Ncol + c] =
                        make_float2(acc[ma][na][2], acc[ma][na][3]);
            }
        }
    }
}

// ---------------- attention logits: al_s/al_d [N,H] ------------------------
__global__ void logits_kernel(const float* __restrict__ hx,
                              const float* __restrict__ a_src,
                              const float* __restrict__ a_dst,
                              float* __restrict__ als, float* __restrict__ ald,
                              int H, int C)
{
    int n = blockIdx.x;
    int warp = threadIdx.x >> 5;
    int lane = threadIdx.x & 31;
    if (warp >= H) return;
    const float* row = hx + (size_t)n * H * C + warp * C;
    float ss = 0.f, sd = 0.f;
    for (int c = lane; c < C; c += 32) {
        float v = row[c];
        ss += v * a_src[warp * C + c];
        sd += v * a_dst[warp * C + c];
    }
#pragma unroll
    for (int s = 16; s > 0; s >>= 1) {
        ss += __shfl_down_sync(0xffffffffu, ss, s);
        sd += __shfl_down_sync(0xffffffffu, sd, s);
    }
    if (lane == 0) {
        als[n * H + warp] = ss;
        ald[n * H + warp] = sd;
    }
}

// ---------------- per-dst softmax + aggregation ----------------------------
__global__ __launch_bounds__(256) void aggregate_kernel(
    const float* __restrict__ hx,
    const float* __restrict__ als, const float* __restrict__ ald,
    const float* __restrict__ bias, float* __restrict__ out,
    int H, int C, int act)
{
    int n   = blockIdx.x;
    int HC  = H * C;
    int tid = threadIdx.x;
    int h   = tid % H;
    int w   = tid / H;
    int NW  = 256 / H;

    __shared__ float sm_ald[HMAX];
    __shared__ float scratch[256];
    __shared__ float sm_alpha[256];
    __shared__ int   sm_src[256];

    int e0  = g_off[n];
    int deg = g_off[n + 1] - e0;

    if (tid < H) sm_ald[tid] = ald[(size_t)n * H + tid];
    __syncthreads();
    float myald = sm_ald[h];

    float mx = -1e30f;
    for (int j = w; j < deg; j += NW) {
        int s = g_csr_src[e0 + j];
        float v = als[(size_t)s * H + h] + myald;
        v = (v >= 0.f) ? v : 0.2f * v;
        mx = fmaxf(mx, v);
    }
    scratch[tid] = mx;
    __syncthreads();
    for (int st = NW >> 1; st > 0; st >>= 1) {
        if (w < st) scratch[tid] = fmaxf(scratch[tid], scratch[tid + st * H]);
        __syncthreads();
    }
    float m = scratch[h];
    __syncthreads();

    float sum = 0.f;
    for (int j = w; j < deg; j += NW) {
        int s = g_csr_src[e0 + j];
        float v = als[(size_t)s * H + h] + myald;
        v = (v >= 0.f) ? v : 0.2f * v;
        sum += expf(v - m);
    }
    scratch[tid] = sum;
    __syncthreads();
    for (int st = NW >> 1; st > 0; st >>= 1) {
        if (w < st) scratch[tid] += scratch[tid + st * H];
        __syncthreads();
    }
    float denom = scratch[h] + 1e-16f;
    __syncthreads();

    float acc0 = 0.f, acc1 = 0.f;
    int c0 = tid, c1 = tid + 256;
    int h0 = (c0 < HC) ? (c0 / C) : 0;
    int h1 = (c1 < HC) ? (c1 / C) : 0;

    for (int base = 0; base < deg; base += NW) {
        int j = base + w;
        if (j < deg) {
            int s = g_csr_src[e0 + j];
            if (h == 0) sm_src[w] = s;
            float v = als[(size_t)s * H + h] + myald;
            v = (v >= 0.f) ? v : 0.2f * v;
            sm_alpha[w * H + h] = expf(v - m) / denom;
        }
        __syncthreads();
        int lim = deg - base; if (lim > NW) lim = NW;
        for (int j2 = 0; j2 < lim; j2++) {
            int s = sm_src[j2];
            const float* hrow = hx + (size_t)s * HC;
            float a0 = sm_alpha[j2 * H + h0];
            float a1 = sm_alpha[j2 * H + h1];
            if (c0 < HC) acc0 += hrow[c0] * a0;
            if (c1 < HC) acc1 += hrow[c1] * a1;
        }
        __syncthreads();
    }

    if (c0 < HC) {
        float o = acc0 + bias[c0];
        if (act) o = (o > 0.f) ? o : expm1f(o);
        out[(size_t)n * HC + c0] = o;
    }
    if (c1 < HC) {
        float o = acc1 + bias[c1];
        if (act) o = (o > 0.f) ? o : expm1f(o);
        out[(size_t)n * HC + c1] = o;
    }
}

// ---------------- host -----------------------------------------------------
extern "C" void kernel_launch(void* const* d_in, const int* in_sizes, int n_in,
                              void* d_out, int out_size)
{
    const float* x      = (const float*)d_in[0];
    const int*   ei     = (const int*)  d_in[1];
    const float* W0     = (const float*)d_in[2];
    const float* a_src0 = (const float*)d_in[3];
    const float* a_dst0 = (const float*)d_in[4];
    const float* b0     = (const float*)d_in[5];
    const float* W1     = (const float*)d_in[6];
    const float* a_src1 = (const float*)d_in[7];
    const float* a_dst1 = (const float*)d_in[8];
    const float* b1     = (const float*)d_in[9];
    const float* W2     = (const float*)d_in[10];
    const float* a_src2 = (const float*)d_in[11];
    const float* a_dst2 = (const float*)d_in[12];
    const float* b2     = (const float*)d_in[13];
    float* out = (float*)d_out;

    float *hx, *f1, *f2, *als, *ald;
    cudaGetSymbolAddress((void**)&hx,  g_hx);
    cudaGetSymbolAddress((void**)&f1,  g_f1);
    cudaGetSymbolAddress((void**)&f2,  g_f2);
    cudaGetSymbolAddress((void**)&als, g_als);
    cudaGetSymbolAddress((void**)&ald, g_ald);
    __nv_bfloat16 *w0hi, *w0lo, *w1hi, *w1lo, *w2hi, *w2lo;
    cudaGetSymbolAddress((void**)&w0hi, g_w0hi);
    cudaGetSymbolAddress((void**)&w0lo, g_w0lo);
    cudaGetSymbolAddress((void**)&w1hi, g_w1hi);
    cudaGetSymbolAddress((void**)&w1lo, g_w1lo);
    cudaGetSymbolAddress((void**)&w2hi, g_w2hi);
    cudaGetSymbolAddress((void**)&w2lo, g_w2lo);

    // [0] weight splits (one launch)
    split_weights_kernel<<<(W0N + W1N + W2N + 255) / 256, 256>>>(W0, W1, W2);
    // [1..4] CSR build
    zero_deg_kernel<<<(NNODES + 255) / 256, 256>>>();
    count_kernel<<<(NETOT + 255) / 256, 256>>>(ei);
    scan_kernel<<<1, 1024>>>();
    scatter_kernel<<<(NETOT + 255) / 256, 256>>>(ei);

    // ---- layer 0: 256 -> 8x64, ELU      ([5] = gemm, ncu target)
    {
        dim3 grid((NNODES + 127) / 128, 4);
        gemm_mma3_kernel<<<grid, 256>>>(x, w0hi, w0lo, hx, NNODES, 256, 512);
        logits_kernel<<<NNODES, 256>>>(hx, a_src0, a_dst0, als, ald, 8, 64);
        aggregate_kernel<<<NNODES, 256>>>(hx, als, ald, b0, f1, 8, 64, 1);
    }
    // ---- layer 1: 512 -> 8x64, ELU
    {
        dim3 grid((NNODES + 127) / 128, 4);
        gemm_mma3_kernel<<<grid, 256>>>(f1, w1hi, w1lo, hx, NNODES, 512, 512);
        logits_kernel<<<NNODES, 256>>>(hx, a_src1, a_dst1, als, ald, 8, 64);
        aggregate_kernel<<<NNODES, 256>>>(hx, als, ald, b1, f2, 8, 64, 1);
    }
    // ---- layer 2: 512 -> 1x40, no activation, write d_out
    {
        dim3 grid((NNODES + 127) / 128, 1);
        gemm_mma3_kernel<<<grid, 256>>>(f2, w2hi, w2lo, hx, NNODES, 512, 40);
        logits_kernel<<<NNODES, 32>>>(hx, a_src2, a_dst2, als, ald, 1, 40);
        aggregate_kernel<<<NNODES, 256>>>(hx, als, ald, b2, out, 1, 40, 0);
    }
    (void)in_sizes; (void)n_in; (void)out_size;
}

// round 10
// speedup vs baseline: 1.6828x; 1.3254x over previous
#include <cuda_runtime.h>
#include <cuda_bf16.h>
#include <cstdint>
#include <cstddef>

#define NNODES   10000
#define NEDGES   160000
#define NETOT    170000   // + self loops
#define HMAX     8

// ---------------- scratch (device globals; no allocation allowed) ----------
__device__ float g_hx [NNODES * 512];
__device__ float g_f1 [NNODES * 512];
__device__ float g_f2 [NNODES * 512];
__device__ float g_als[NNODES * HMAX];
__device__ float g_ald[NNODES * HMAX];
__device__ int   g_deg[NNODES];
__device__ int   g_off[NNODES + 1];
__device__ int   g_cur[NNODES];
__device__ int   g_csr_src[NETOT];

// bf16 split weight buffers
__device__ __nv_bfloat16 g_w0hi[256 * 512], g_w0lo[256 * 512];
__device__ __nv_bfloat16 g_w1hi[512 * 512], g_w1lo[512 * 512];
__device__ __nv_bfloat16 g_w2hi[512 * 40],  g_w2lo[512 * 40];

#define W0N (256 * 512)
#define W1N (512 * 512)
#define W2N (512 * 40)

// ---------------- combined weight split (one launch) ------------------------
__global__ void split_weights_kernel(const float* __restrict__ W0,
                                     const float* __restrict__ W1,
                                     const float* __restrict__ W2)
{
    int i = blockIdx.x * blockDim.x + threadIdx.x;
    const float* src;
    __nv_bfloat16 *hi, *lo;
    int j;
    if (i < W0N)                   { src = W0; hi = g_w0hi; lo = g_w0lo; j = i; }
    else if (i < W0N + W1N)        { src = W1; hi = g_w1hi; lo = g_w1lo; j = i - W0N; }
    else if (i < W0N + W1N + W2N)  { src = W2; hi = g_w2hi; lo = g_w2lo; j = i - W0N - W1N; }
    else return;
    float x = src[j];
    __nv_bfloat16 h = __float2bfloat16_rn(x);
    hi[j] = h;
    lo[j] = __float2bfloat16_rn(x - __bfloat162float(h));
}

// ---------------- CSR build ------------------------------------------------
__global__ void zero_deg_kernel() {
    int i = blockIdx.x * blockDim.x + threadIdx.x;
    if (i < NNODES) g_deg[i] = 0;
}

__global__ void count_kernel(const int* __restrict__ ei) {
    int i = blockIdx.x * blockDim.x + threadIdx.x;
    if (i >= NETOT) return;
    int dst = (i < NEDGES) ? ei[NEDGES + i] : (i - NEDGES);
    atomicAdd(&g_deg[dst], 1);
}

__global__ void scan_kernel() {
    __shared__ int sm[1024];
    int tid = threadIdx.x;
    const int SEG = (NNODES + 1023) / 1024;
    int beg = tid * SEG;
    int end = beg + SEG; if (end > NNODES) end = NNODES;
    int s = 0;
    for (int i = beg; i < end; i++) s += g_deg[i];
    sm[tid] = s;
    __syncthreads();
    for (int d = 1; d < 1024; d <<= 1) {
        int v = (tid >= d) ? sm[tid - d] : 0;
        __syncthreads();
        sm[tid] += v;
        __syncthreads();
    }
    int run = (tid > 0) ? sm[tid - 1] : 0;
    for (int i = beg; i < end; i++) {
        g_off[i] = run;
        g_cur[i] = run;
        run += g_deg[i];
    }
    if (tid == 1023) g_off[NNODES] = sm[1023];
}

__global__ void scatter_kernel(const int* __restrict__ ei) {
    int i = blockIdx.x * blockDim.x + threadIdx.x;
    if (i >= NETOT) return;
    int src, dst;
    if (i < NEDGES) { src = ei[i]; dst = ei[NEDGES + i]; }
    else            { src = i - NEDGES; dst = src; }
    int p = atomicAdd(&g_cur[dst], 1);
    g_csr_src[p] = src;
}

// ---------------- tensor-core GEMM, 3 products in ONE k-loop ----------------
// C = Ahi@Bhi + Ahi@Blo + Alo@Bhi   ; A fp32 [M,K] split in-kernel.
// Block tile 128x64, BK=32, 8 warps (4x2), warp tile 32x32, mma m16n8k16.
// Register double-buffered global->smem pipeline.
#define RS 40   // smem row stride in bf16 (conflict-free fragment loads)

__device__ __forceinline__ void mma16816(float* c, const uint32_t* a, const uint32_t* b)
{
    asm volatile(
        "mma.sync.aligned.m16n8k16.row.col.f32.bf16.bf16.f32 "
        "{%0,%1,%2,%3}, {%4,%5,%6,%7}, {%8,%9}, {%0,%1,%2,%3};\n"
        : "+f"(c[0]), "+f"(c[1]), "+f"(c[2]), "+f"(c[3])
        : "r"(a[0]), "r"(a[1]), "r"(a[2]), "r"(a[3]), "r"(b[0]), "r"(b[1]));
}

__global__ __launch_bounds__(256) void gemm_mma3_kernel(
    const float* __restrict__ A,
    const __nv_bfloat16* __restrict__ Bhi, const __nv_bfloat16* __restrict__ Blo,
    float* __restrict__ C, int M, int K, int Ncol)
{
    __shared__ __align__(16) __nv_bfloat16 Ash[128 * RS];
    __shared__ __align__(16) __nv_bfloat16 Asl[128 * RS];
    __shared__ __align__(16) __nv_bfloat16 Bsh[64 * RS];
    __shared__ __align__(16) __nv_bfloat16 Bsl[64 * RS];

    int tid  = threadIdx.x;
    int wid  = tid >> 5;
    int lane = tid & 31;
    int g    = lane >> 2;          // 0..7
    int tig  = lane & 3;           // 0..3
    int wm   = wid & 3;            // M dir 0..3
    int wn   = wid >> 2;           // N dir 0..1
    int wrow = wm * 32;
    int wcol = wn * 32;
    int row0 = blockIdx.x * 128;
    int col0 = blockIdx.y * 64;

    // A load mapping: 1024 float4 chunks; this thread owns 4
    int a_row[4], a_col[4];
#pragma unroll
    for (int i = 0; i < 4; i++) {
        int e = tid + i * 256;
        a_row[i] = e >> 3;
        a_col[i] = (e & 7) * 4;
    }
    // B load mapping: 512 chunks of 4 bf16; this thread owns 2 per buffer
    int b_kk[2], b_nn[2];
#pragma unroll
    for (int i = 0; i < 2; i++) {
        int e = tid + i * 256;
        b_kk[i] = e >> 4;          // 0..31
        b_nn[i] = (e & 15) * 4;    // 0..60
    }

    float acc[2][4][4];
#pragma unroll
    for (int i = 0; i < 2; i++)
#pragma unroll
        for (int j = 0; j < 4; j++)
#pragma unroll
            for (int q = 0; q < 4; q++) acc[i][j][q] = 0.f;

    float4 pa[4];
    uint2  pbh[2], pbl[2];

    // prefetch k0 = 0
#pragma unroll
    for (int i = 0; i < 4; i++) {
        pa[i] = make_float4(0.f, 0.f, 0.f, 0.f);
        int gr = row0 + a_row[i];
        if (gr < M) pa[i] = *(const float4*)(A + (size_t)gr * K + a_col[i]);
    }
#pragma unroll
    for (int i = 0; i < 2; i++) {
        pbh[i] = make_uint2(0u, 0u); pbl[i] = make_uint2(0u, 0u);
        if (col0 + b_nn[i] < Ncol) {
            size_t off = (size_t)b_kk[i] * Ncol + col0 + b_nn[i];
            pbh[i] = *(const uint2*)(Bhi + off);
            pbl[i] = *(const uint2*)(Blo + off);
        }
    }

#pragma unroll 1
    for (int k0 = 0; k0 < K; k0 += 32) {
        // ---- store current tile to smem (split A on the fly)
#pragma unroll
        for (int i = 0; i < 4; i++) {
            float f[4] = {pa[i].x, pa[i].y, pa[i].z, pa[i].w};
            __nv_bfloat16 h[4], l[4];
#pragma unroll
            for (int q = 0; q < 4; q++) {
                h[q] = __float2bfloat16_rn(f[q]);
                l[q] = __float2bfloat16_rn(f[q] - __bfloat162float(h[q]));
            }
            *(uint2*)&Ash[a_row[i] * RS + a_col[i]] = *(uint2*)h;
            *(uint2*)&Asl[a_row[i] * RS + a_col[i]] = *(uint2*)l;
        }
#pragma unroll
        for (int i = 0; i < 2; i++) {
            __nv_bfloat16 th[4], tl[4];
            *(uint2*)th = pbh[i];
            *(uint2*)tl = pbl[i];
#pragma unroll
            for (int j = 0; j < 4; j++) {
                Bsh[(b_nn[i] + j) * RS + b_kk[i]] = th[j];
                Bsl[(b_nn[i] + j) * RS + b_kk[i]] = tl[j];
            }
        }
        __syncthreads();

        // ---- prefetch next tile (overlaps with mma below)
        if (k0 + 32 < K) {
#pragma unroll
            for (int i = 0; i < 4; i++) {
                pa[i] = make_float4(0.f, 0.f, 0.f, 0.f);
                int gr = row0 + a_row[i];
                if (gr < M) pa[i] = *(const float4*)(A + (size_t)gr * K + k0 + 32 + a_col[i]);
            }
#pragma unroll
            for (int i = 0; i < 2; i++) {
                pbh[i] = make_uint2(0u, 0u); pbl[i] = make_uint2(0u, 0u);
                if (col0 + b_nn[i] < Ncol) {
                    size_t off = (size_t)(k0 + 32 + b_kk[i]) * Ncol + col0 + b_nn[i];
                    pbh[i] = *(const uint2*)(Bhi + off);
                    pbl[i] = *(const uint2*)(Blo + off);
                }
            }
        }

        // ---- compute on smem tile
#pragma unroll
        for (int kk16 = 0; kk16 < 2; kk16++) {
            int kb = kk16 * 16 + tig * 2;
            uint32_t ahi[2][4], alo[2][4];
#pragma unroll
            for (int ma = 0; ma < 2; ma++) {
                int r = wrow + ma * 16 + g;
                const uint32_t* ph0 = (const uint32_t*)&Ash[r * RS + kb];
                const uint32_t* ph1 = (const uint32_t*)&Ash[(r + 8) * RS + kb];
                ahi[ma][0] = ph0[0]; ahi[ma][1] = ph1[0];
                ahi[ma][2] = ph0[4]; ahi[ma][3] = ph1[4];
                const uint32_t* pl0 = (const uint32_t*)&Asl[r * RS + kb];
                const uint32_t* pl1 = (const uint32_t*)&Asl[(r + 8) * RS + kb];
                alo[ma][0] = pl0[0]; alo[ma][1] = pl1[0];
                alo[ma][2] = pl0[4]; alo[ma][3] = pl1[4];
            }
#pragma unroll
            for (int na = 0; na < 4; na++) {
                int n = wcol + na * 8 + g;
                const uint32_t* pb = (const uint32_t*)&Bsh[n * RS + kb];
                uint32_t bh[2] = { pb[0], pb[4] };
                const uint32_t* pl = (const uint32_t*)&Bsl[n * RS + kb];
                uint32_t bl[2] = { pl[0], pl[4] };
#pragma unroll
                for (int ma = 0; ma < 2; ma++) {
                    mma16816(acc[ma][na], ahi[ma], bh);
                    mma16816(acc[ma][na], ahi[ma], bl);
                    mma16816(acc[ma][na], alo[ma], bh);
                }
            }
        }
        __syncthreads();
    }

    // ---- epilogue
#pragma unroll
    for (int ma = 0; ma < 2; ma++) {
#pragma unroll
        for (int na = 0; na < 4; na++) {
            int r = row0 + wrow + ma * 16 + g;
            int c = col0 + wcol + na * 8 + tig * 2;
            if (c < Ncol) {
                if (r < M)
                    *(float2*)&C[(size_t)r * Ncol + c] =
                        make_float2(acc[ma][na][0], acc[ma][na][1]);
                if (r + 8 < M)
                    *(float2*)&C[(size_t)(r + 8) * Ncol + c] =
                        make_float2(acc[ma][na][2], acc[ma][na][3]);
            }
        }
    }
}

// ---------------- attention logits: al_s/al_d [N,H] ------------------------
__global__ void logits_kernel(const float* __restrict__ hx,
                              const float* __restrict__ a_src,
                              const float* __restrict__ a_dst,
                              float* __restrict__ als, float* __restrict__ ald,
                              int H, int C)
{
    int n = blockIdx.x;
    int warp = threadIdx.x >> 5;
    int lane = threadIdx.x & 31;
    if (warp >= H) return;
    const float* row = hx + (size_t)n * H * C + warp * C;
    float ss = 0.f, sd = 0.f;
    for (int c = lane; c < C; c += 32) {
        float v = row[c];
        ss += v * a_src[warp * C + c];
        sd += v * a_dst[warp * C + c];
    }
#pragma unroll
    for (int s = 16; s > 0; s >>= 1) {
        ss += __shfl_down_sync(0xffffffffu, ss, s);
        sd += __shfl_down_sync(0xffffffffu, sd, s);
    }
    if (lane == 0) {
        als[n * H + warp] = ss;
        ald[n * H + warp] = sd;
    }
}

// ---------------- per-dst softmax + aggregation ----------------------------
__global__ __launch_bounds__(256) void aggregate_kernel(
    const float* __restrict__ hx,
    const float* __restrict__ als, const float* __restrict__ ald,
    const float* __restrict__ bias, float* __restrict__ out,
    int H, int C, int act)
{
    int n   = blockIdx.x;
    int HC  = H * C;
    int tid = threadIdx.x;
    int h   = tid % H;
    int w   = tid / H;
    int NW  = 256 / H;

    __shared__ float sm_ald[HMAX];
    __shared__ float scratch[256];
    __shared__ float sm_alpha[256];
    __shared__ int   sm_src[256];

    int e0  = g_off[n];
    int deg = g_off[n + 1] - e0;

    if (tid < H) sm_ald[tid] = ald[(size_t)n * H + tid];
    __syncthreads();
    float myald = sm_ald[h];

    float mx = -1e30f;
    for (int j = w; j < deg; j += NW) {
        int s = g_csr_src[e0 + j];
        float v = als[(size_t)s * H + h] + myald;
        v = (v >= 0.f) ? v : 0.2f * v;
        mx = fmaxf(mx, v);
    }
    scratch[tid] = mx;
    __syncthreads();
    for (int st = NW >> 1; st > 0; st >>= 1) {
        if (w < st) scratch[tid] = fmaxf(scratch[tid], scratch[tid + st * H]);
        __syncthreads();
    }
    float m = scratch[h];
    __syncthreads();

    float sum = 0.f;
    for (int j = w; j < deg; j += NW) {
        int s = g_csr_src[e0 + j];
        float v = als[(size_t)s * H + h] + myald;
        v = (v >= 0.f) ? v : 0.2f * v;
        sum += expf(v - m);
    }
    scratch[tid] = sum;
    __syncthreads();
    for (int st = NW >> 1; st > 0; st >>= 1) {
        if (w < st) scratch[tid] += scratch[tid + st * H];
        __syncthreads();
    }
    float denom = scratch[h] + 1e-16f;
    __syncthreads();

    float acc0 = 0.f, acc1 = 0.f;
    int c0 = tid, c1 = tid + 256;
    int h0 = (c0 < HC) ? (c0 / C) : 0;
    int h1 = (c1 < HC) ? (c1 / C) : 0;

    for (int base = 0; base < deg; base += NW) {
        int j = base + w;
        if (j < deg) {
            int s = g_csr_src[e0 + j];
            if (h == 0) sm_src[w] = s;
            float v = als[(size_t)s * H + h] + myald;
            v = (v >= 0.f) ? v : 0.2f * v;
            sm_alpha[w * H + h] = expf(v - m) / denom;
        }
        __syncthreads();
        int lim = deg - base; if (lim > NW) lim = NW;
        for (int j2 = 0; j2 < lim; j2++) {
            int s = sm_src[j2];
            const float* hrow = hx + (size_t)s * HC;
            float a0 = sm_alpha[j2 * H + h0];
            float a1 = sm_alpha[j2 * H + h1];
            if (c0 < HC) acc0 += hrow[c0] * a0;
            if (c1 < HC) acc1 += hrow[c1] * a1;
        }
        __syncthreads();
    }

    if (c0 < HC) {
        float o = acc0 + bias[c0];
        if (act) o = (o > 0.f) ? o : expm1f(o);
        out[(size_t)n * HC + c0] = o;
    }
    if (c1 < HC) {
        float o = acc1 + bias[c1];
        if (act) o = (o > 0.f) ? o : expm1f(o);
        out[(size_t)n * HC + c1] = o;
    }
}

// ---------------- host -----------------------------------------------------
extern "C" void kernel_launch(void* const* d_in, const int* in_sizes, int n_in,
                              void* d_out, int out_size)
{
    const float* x      = (const float*)d_in[0];
    const int*   ei     = (const int*)  d_in[1];
    const float* W0     = (const float*)d_in[2];
    const float* a_src0 = (const float*)d_in[3];
    const float* a_dst0 = (const float*)d_in[4];
    const float* b0     = (const float*)d_in[5];
    const float* W1     = (const float*)d_in[6];
    const float* a_src1 = (const float*)d_in[7];
    const float* a_dst1 = (const float*)d_in[8];
    const float* b1     = (const float*)d_in[9];
    const float* W2     = (const float*)d_in[10];
    const float* a_src2 = (const float*)d_in[11];
    const float* a_dst2 = (const float*)d_in[12];
    const float* b2     = (const float*)d_in[13];
    float* out = (float*)d_out;

    float *hx, *f1, *f2, *als, *ald;
    cudaGetSymbolAddress((void**)&hx,  g_hx);
    cudaGetSymbolAddress((void**)&f1,  g_f1);
    cudaGetSymbolAddress((void**)&f2,  g_f2);
    cudaGetSymbolAddress((void**)&als, g_als);
    cudaGetSymbolAddress((void**)&ald, g_ald);
    __nv_bfloat16 *w0hi, *w0lo, *w1hi, *w1lo, *w2hi, *w2lo;
    cudaGetSymbolAddress((void**)&w0hi, g_w0hi);
    cudaGetSymbolAddress((void**)&w0lo, g_w0lo);
    cudaGetSymbolAddress((void**)&w1hi, g_w1hi);
    cudaGetSymbolAddress((void**)&w1lo, g_w1lo);
    cudaGetSymbolAddress((void**)&w2hi, g_w2hi);
    cudaGetSymbolAddress((void**)&w2lo, g_w2lo);

    // [0] weight splits
    split_weights_kernel<<<(W0N + W1N + W2N + 255) / 256, 256>>>(W0, W1, W2);
    // [1..2] CSR build part 1
    zero_deg_kernel<<<(NNODES + 255) / 256, 256>>>();
    count_kernel<<<(NETOT + 255) / 256, 256>>>(ei);
    // [3] gemm layer0 — positioned here so ncu (-s 5 -c 1) profiles it
    {
        dim3 grid((NNODES + 127) / 128, 8);
        gemm_mma3_kernel<<<grid, 256>>>(x, w0hi, w0lo, hx, NNODES, 256, 512);
    }
    // [4..5] CSR build part 2
    scan_kernel<<<1, 1024>>>();
    scatter_kernel<<<(NETOT + 255) / 256, 256>>>(ei);

    // ---- layer 0 rest
    logits_kernel<<<NNODES, 256>>>(hx, a_src0, a_dst0, als, ald, 8, 64);
    aggregate_kernel<<<NNODES, 256>>>(hx, als, ald, b0, f1, 8, 64, 1);
    // ---- layer 1
    {
        dim3 grid((NNODES + 127) / 128, 8);
        gemm_mma3_kernel<<<grid, 256>>>(f1, w1hi, w1lo, hx, NNODES, 512, 512);
        logits_kernel<<<NNODES, 256>>>(hx, a_src1, a_dst1, als, ald, 8, 64);
        aggregate_kernel<<<NNODES, 256>>>(hx, als, ald, b1, f2, 8, 64, 1);
    }
    // ---- layer 2
    {
        dim3 grid((NNODES + 127) / 128, 1);
        gemm_mma3_kernel<<<grid, 256>>>(f2, w2hi, w2lo, hx, NNODES, 512, 40);
        logits_kernel<<<NNODES, 32>>>(hx, a_src2, a_dst2, als, ald, 1, 40);
        aggregate_kernel<<<NNODES, 256>>>(hx, als, ald, b2, out, 1, 40, 0);
    }
    (void)in_sizes; (void)n_in; (void)out_size;
}

// round 14
// speedup vs baseline: 2.2928x; 1.3625x over previous
#include <cuda_runtime.h>
#include <cuda_bf16.h>
#include <cstdint>
#include <cstddef>

#define NNODES   10000
#define NEDGES   160000
#define NETOT    170000   // + self loops
#define HMAX     8

// ---------------- scratch (device globals; no allocation allowed) ----------
__device__ float g_hx [NNODES * 512];
__device__ float g_f1 [NNODES * 512];
__device__ float g_f2 [NNODES * 512];
__device__ float g_als[NNODES * HMAX];
__device__ float g_ald[NNODES * HMAX];
__device__ int   g_deg[NNODES];
__device__ int   g_off[NNODES + 1];
__device__ int   g_cur[NNODES];
__device__ int   g_csr_src[NETOT];

// bf16 split weight buffers
__device__ __nv_bfloat16 g_w0hi[256 * 512], g_w0lo[256 * 512];
__device__ __nv_bfloat16 g_w1hi[512 * 512], g_w1lo[512 * 512];
__device__ __nv_bfloat16 g_w2hi[512 * 40],  g_w2lo[512 * 40];

#define W0N (256 * 512)
#define W1N (512 * 512)
#define W2N (512 * 40)

// ---------------- combined weight split (one launch) ------------------------
__global__ void split_weights_kernel(const float* __restrict__ W0,
                                     const float* __restrict__ W1,
                                     const float* __restrict__ W2)
{
    int i = blockIdx.x * blockDim.x + threadIdx.x;
    const float* src;
    __nv_bfloat16 *hi, *lo;
    int j;
    if (i < W0N)                   { src = W0; hi = g_w0hi; lo = g_w0lo; j = i; }
    else if (i < W0N + W1N)        { src = W1; hi = g_w1hi; lo = g_w1lo; j = i - W0N; }
    else if (i < W0N + W1N + W2N)  { src = W2; hi = g_w2hi; lo = g_w2lo; j = i - W0N - W1N; }
    else return;
    float x = src[j];
    __nv_bfloat16 h = __float2bfloat16_rn(x);
    hi[j] = h;
    lo[j] = __float2bfloat16_rn(x - __bfloat162float(h));
}

// ---------------- CSR build ------------------------------------------------
__global__ void zero_deg_kernel() {
    int i = blockIdx.x * blockDim.x + threadIdx.x;
    if (i < NNODES) g_deg[i] = 0;
}

__global__ void count_kernel(const int* __restrict__ ei) {
    int i = blockIdx.x * blockDim.x + threadIdx.x;
    if (i >= NETOT) return;
    int dst = (i < NEDGES) ? ei[NEDGES + i] : (i - NEDGES);
    atomicAdd(&g_deg[dst], 1);
}

__global__ void scan_kernel() {
    __shared__ int sm[1024];
    int tid = threadIdx.x;
    const int SEG = (NNODES + 1023) / 1024;
    int beg = tid * SEG;
    int end = beg + SEG; if (end > NNODES) end = NNODES;
    int s = 0;
    for (int i = beg; i < end; i++) s += g_deg[i];
    sm[tid] = s;
    __syncthreads();
    for (int d = 1; d < 1024; d <<= 1) {
        int v = (tid >= d) ? sm[tid - d] : 0;
        __syncthreads();
        sm[tid] += v;
        __syncthreads();
    }
    int run = (tid > 0) ? sm[tid - 1] : 0;
    for (int i = beg; i < end; i++) {
        g_off[i] = run;
        g_cur[i] = run;
        run += g_deg[i];
    }
    if (tid == 1023) g_off[NNODES] = sm[1023];
}

__global__ void scatter_kernel(const int* __restrict__ ei) {
    int i = blockIdx.x * blockDim.x + threadIdx.x;
    if (i >= NETOT) return;
    int src, dst;
    if (i < NEDGES) { src = ei[i]; dst = ei[NEDGES + i]; }
    else            { src = i - NEDGES; dst = src; }
    int p = atomicAdd(&g_cur[dst], 1);
    g_csr_src[p] = src;
}

// ---------------- tensor-core GEMM, 3 products in ONE k-loop ----------------
// C = Ahi@Bhi + Ahi@Blo + Alo@Bhi ; A fp32 [M,K] split in-kernel.
// Block tile 128x64, BK=32, 8 warps (4x2), warp tile 32x32, mma m16n8k16.
// ldmatrix fragment loads; register double-buffered gmem->smem pipeline.
#define RS  40   // A smem row stride (bf16): 80B, 16B aligned, LDSM conflict-free
#define RSB 72   // B smem row stride (bf16): 144B, 16B aligned, LDSM conflict-free

__device__ __forceinline__ void mma16816(float* c, const uint32_t* a, const uint32_t* b)
{
    asm volatile(
        "mma.sync.aligned.m16n8k16.row.col.f32.bf16.bf16.f32 "
        "{%0,%1,%2,%3}, {%4,%5,%6,%7}, {%8,%9}, {%0,%1,%2,%3};\n"
        : "+f"(c[0]), "+f"(c[1]), "+f"(c[2]), "+f"(c[3])
        : "r"(a[0]), "r"(a[1]), "r"(a[2]), "r"(a[3]), "r"(b[0]), "r"(b[1]));
}

__device__ __forceinline__ void ldsm4(uint32_t* r, uint32_t addr)
{
    asm volatile("ldmatrix.sync.aligned.m8n8.x4.shared.b16 {%0,%1,%2,%3}, [%4];"
        : "=r"(r[0]), "=r"(r[1]), "=r"(r[2]), "=r"(r[3]) : "r"(addr));
}

__device__ __forceinline__ void ldsm4t(uint32_t* r, uint32_t addr)
{
    asm volatile("ldmatrix.sync.aligned.m8n8.x4.trans.shared.b16 {%0,%1,%2,%3}, [%4];"
        : "=r"(r[0]), "=r"(r[1]), "=r"(r[2]), "=r"(r[3]) : "r"(addr));
}

__global__ __launch_bounds__(256, 2) void gemm_mma3_kernel(
    const float* __restrict__ A,
    const __nv_bfloat16* __restrict__ Bhi, const __nv_bfloat16* __restrict__ Blo,
    float* __restrict__ C, int M, int K, int Ncol)
{
    __shared__ __align__(16) __nv_bfloat16 Ash[128 * RS];
    __shared__ __align__(16) __nv_bfloat16 Asl[128 * RS];
    __shared__ __align__(16) __nv_bfloat16 Bsh[32 * RSB];
    __shared__ __align__(16) __nv_bfloat16 Bsl[32 * RSB];

    int tid  = threadIdx.x;
    int wid  = tid >> 5;
    int lane = tid & 31;
    int g    = lane >> 2;          // 0..7 (C row within 8)
    int tig  = lane & 3;           // 0..3 (C col pair)
    int wm   = wid & 3;
    int wn   = wid >> 2;
    int wrow = wm * 32;
    int wcol = wn * 32;
    int row0 = blockIdx.x * 128;
    int col0 = blockIdx.y * 64;

    // gmem->smem load mappings
    int a_row[4], a_col[4];
#pragma unroll
    for (int i = 0; i < 4; i++) {
        int e = tid + i * 256;
        a_row[i] = e >> 3;
        a_col[i] = (e & 7) * 4;
    }
    int b_kk[2], b_nn[2];
#pragma unroll
    for (int i = 0; i < 2; i++) {
        int e = tid + i * 256;
        b_kk[i] = e >> 4;          // 0..31
        b_nn[i] = (e & 15) * 4;    // 0..60
    }

    // ldmatrix lane addressing
    int q   = lane >> 3;           // matrix group 0..3
    int iL  = lane & 7;
    int roff = ((q & 1) ? 8 : 0) + iL;   // row (A) / k-row (B)
    int soff = (q >> 1) ? 8 : 0;         // k offset (A) / n offset (B)
    uint32_t ashL = (uint32_t)__cvta_generic_to_shared(Ash) + ((wrow + roff) * RS + soff) * 2;
    uint32_t aslL = (uint32_t)__cvta_generic_to_shared(Asl) + ((wrow + roff) * RS + soff) * 2;
    uint32_t bshL = (uint32_t)__cvta_generic_to_shared(Bsh) + (roff * RSB + wcol + soff) * 2;
    uint32_t bslL = (uint32_t)__cvta_generic_to_shared(Bsl) + (roff * RSB + wcol + soff) * 2;

    float acc[2][4][4];
#pragma unroll
    for (int i = 0; i < 2; i++)
#pragma unroll
        for (int j = 0; j < 4; j++)
#pragma unroll
            for (int p = 0; p < 4; p++) acc[i][j][p] = 0.f;

    float4 pa[4];
    uint2  pbh[2], pbl[2];

    // prefetch k0 = 0
#pragma unroll
    for (int i = 0; i < 4; i++) {
        pa[i] = make_float4(0.f, 0.f, 0.f, 0.f);
        int gr = row0 + a_row[i];
        if (gr < M) pa[i] = *(const float4*)(A + (size_t)gr * K + a_col[i]);
    }
#pragma unroll
    for (int i = 0; i < 2; i++) {
        pbh[i] = make_uint2(0u, 0u); pbl[i] = make_uint2(0u, 0u);
        if (col0 + b_nn[i] < Ncol) {
            size_t off = (size_t)b_kk[i] * Ncol + col0 + b_nn[i];
            pbh[i] = *(const uint2*)(Bhi + off);
            pbl[i] = *(const uint2*)(Blo + off);
        }
    }

#pragma unroll 1
    for (int k0 = 0; k0 < K; k0 += 32) {
        // ---- store current tile to smem (split A on the fly; B stays k-major)
#pragma unroll
        for (int i = 0; i < 4; i++) {
            float f[4] = {pa[i].x, pa[i].y, pa[i].z, pa[i].w};
            __nv_bfloat16 h[4], l[4];
#pragma unroll
            for (int p = 0; p < 4; p++) {
                h[p] = __float2bfloat16_rn(f[p]);
                l[p] = __float2bfloat16_rn(f[p] - __bfloat162float(h[p]));
            }
            *(uint2*)&Ash[a_row[i] * RS + a_col[i]] = *(uint2*)h;
            *(uint2*)&Asl[a_row[i] * RS + a_col[i]] = *(uint2*)l;
        }
#pragma unroll
        for (int i = 0; i < 2; i++) {
            *(uint2*)&Bsh[b_kk[i] * RSB + b_nn[i]] = pbh[i];
            *(uint2*)&Bsl[b_kk[i] * RSB + b_nn[i]] = pbl[i];
        }
        __syncthreads();

        // ---- prefetch next tile (overlaps with mma below)
        if (k0 + 32 < K) {
#pragma unroll
            for (int i = 0; i < 4; i++) {
                pa[i] = make_float4(0.f, 0.f, 0.f, 0.f);
                int gr = row0 + a_row[i];
                if (gr < M) pa[i] = *(const float4*)(A + (size_t)gr * K + k0 + 32 + a_col[i]);
            }
#pragma unroll
            for (int i = 0; i < 2; i++) {
                pbh[i] = make_uint2(0u, 0u); pbl[i] = make_uint2(0u, 0u);
                if (col0 + b_nn[i] < Ncol) {
                    size_t off = (size_t)(k0 + 32 + b_kk[i]) * Ncol + col0 + b_nn[i];
                    pbh[i] = *(const uint2*)(Bhi + off);
                    pbl[i] = *(const uint2*)(Blo + off);
                }
            }
        }

        // ---- compute on smem tile via ldmatrix
#pragma unroll
        for (int kk16 = 0; kk16 < 2; kk16++) {
            uint32_t ah[2][4], al_[2][4];
#pragma unroll
            for (int ma = 0; ma < 2; ma++) {
                uint32_t aoff = ((uint32_t)(ma * 16 * RS + kk16 * 16)) * 2;
                ldsm4(ah[ma],  ashL + aoff);
                ldsm4(al_[ma], aslL + aoff);
            }
            uint32_t bh[2][4], bl[2][4];
#pragma unroll
            for (int p = 0; p < 2; p++) {
                uint32_t boff = ((uint32_t)(kk16 * 16 * RSB + p * 16)) * 2;
                ldsm4t(bh[p], bshL + boff);
                ldsm4t(bl[p], bslL + boff);
            }
#pragma unroll
            for (int na = 0; na < 4; na++) {
                const uint32_t* bph = &bh[na >> 1][(na & 1) * 2];
                const uint32_t* bpl = &bl[na >> 1][(na & 1) * 2];
#pragma unroll
                for (int ma = 0; ma < 2; ma++) {
                    mma16816(acc[ma][na], ah[ma],  bph);
                    mma16816(acc[ma][na], ah[ma],  bpl);
                    mma16816(acc[ma][na], al_[ma], bph);
                }
            }
        }
        __syncthreads();
    }

    // ---- epilogue
#pragma unroll
    for (int ma = 0; ma < 2; ma++) {
#pragma unroll
        for (int na = 0; na < 4; na++) {
            int r = row0 + wrow + ma * 16 + g;
            int c = col0 + wcol + na * 8 + tig * 2;
            if (c < Ncol) {
                if (r < M)
                    *(float2*)&C[(size_t)r * Ncol + c] =
                        make_float2(acc[ma][na][0], acc[ma][na][1]);
                if (r + 8 < M)
                    *(float2*)&C[(size_t)(r + 8) * Ncol + c] =
                        make_float2(acc[ma][na][2], acc[ma][na][3]);
            }
        }
    }
}

// ---------------- attention logits: al_s/al_d [N,H] ------------------------
__global__ void logits_kernel(const float* __restrict__ hx,
                              const float* __restrict__ a_src,
                              const float* __restrict__ a_dst,
                              float* __restrict__ als, float* __restrict__ ald,
                              int H, int C)
{
    int n = blockIdx.x;
    int warp = threadIdx.x >> 5;
    int lane = threadIdx.x & 31;
    if (warp >= H) return;
    const float* row = hx + (size_t)n * H * C + warp * C;
    float ss = 0.f, sd = 0.f;
    for (int c = lane; c < C; c += 32) {
        float v = row[c];
        ss += v * a_src[warp * C + c];
        sd += v * a_dst[warp * C + c];
    }
#pragma unroll
    for (int s = 16; s > 0; s >>= 1) {
        ss += __shfl_down_sync(0xffffffffu, ss, s);
        sd += __shfl_down_sync(0xffffffffu, sd, s);
    }
    if (lane == 0) {
        als[n * H + warp] = ss;
        ald[n * H + warp] = sd;
    }
}

// ---------------- per-dst softmax + aggregation (single pass) ---------------
// softmax is shift-invariant and logits are tame => no max pass; accumulate
// unnormalized Σ ex*hx and Σ ex, divide at the end.
__global__ __launch_bounds__(256) void aggregate_kernel(
    const float* __restrict__ hx,
    const float* __restrict__ als, const float* __restrict__ ald,
    const float* __restrict__ bias, float* __restrict__ out,
    int H, int C, int act)
{
    int n   = blockIdx.x;
    int HC  = H * C;
    int tid = threadIdx.x;
    int h   = tid % H;
    int w   = tid / H;
    int NW  = 256 / H;

    __shared__ float sm_ald[HMAX];
    __shared__ float sm_ex[256];
    __shared__ float scratch[256];
    __shared__ int   sm_src[256];

    int e0  = g_off[n];
    int deg = g_off[n + 1] - e0;

    if (tid < H) sm_ald[tid] = ald[(size_t)n * H + tid];
    __syncthreads();
    float myald = sm_ald[h];

    float acc0 = 0.f, acc1 = 0.f, psum = 0.f;
    int c0 = tid, c1 = tid + 256;
    int h0 = (c0 < HC) ? (c0 / C) : 0;
    int h1 = (c1 < HC) ? (c1 / C) : 0;

    for (int base = 0; base < deg; base += NW) {
        int j = base + w;
        if (j < deg) {
            int s = g_csr_src[e0 + j];
            if (h == 0) sm_src[w] = s;
            float v = als[(size_t)s * H + h] + myald;
            v = (v >= 0.f) ? v : 0.2f * v;
            float ex = expf(v);
            sm_ex[w * H + h] = ex;
            psum += ex;
        }
        __syncthreads();
        int lim = deg - base; if (lim > NW) lim = NW;
        for (int j2 = 0; j2 < lim; j2++) {
            int s = sm_src[j2];
            const float* hrow = hx + (size_t)s * HC;
            float a0 = sm_ex[j2 * H + h0];
            float a1 = sm_ex[j2 * H + h1];
            if (c0 < HC) acc0 += hrow[c0] * a0;
            if (c1 < HC) acc1 += hrow[c1] * a1;
        }
        __syncthreads();
    }

    // reduce psum over w (per head)
    scratch[tid] = psum;
    __syncthreads();
    for (int st = NW >> 1; st > 0; st >>= 1) {
        if (w < st) scratch[tid] += scratch[tid + st * H];
        __syncthreads();
    }
    float d0 = scratch[h0] + 1e-16f;
    float d1 = scratch[h1] + 1e-16f;

    if (c0 < HC) {
        float o = acc0 / d0 + bias[c0];
        if (act) o = (o > 0.f) ? o : expm1f(o);
        out[(size_t)n * HC + c0] = o;
    }
    if (c1 < HC) {
        float o = acc1 / d1 + bias[c1];
        if (act) o = (o > 0.f) ? o : expm1f(o);
        out[(size_t)n * HC + c1] = o;
    }
}

// ---------------- host -----------------------------------------------------
extern "C" void kernel_launch(void* const* d_in, const int* in_sizes, int n_in,
                              void* d_out, int out_size)
{
    const float* x      = (const float*)d_in[0];
    const int*   ei     = (const int*)  d_in[1];
    const float* W0     = (const float*)d_in[2];
    const float* a_src0 = (const float*)d_in[3];
    const float* a_dst0 = (const float*)d_in[4];
    const float* b0     = (const float*)d_in[5];
    const float* W1     = (const float*)d_in[6];
    const float* a_src1 = (const float*)d_in[7];
    const float* a_dst1 = (const float*)d_in[8];
    const float* b1     = (const float*)d_in[9];
    const float* W2     = (const float*)d_in[10];
    const float* a_src2 = (const float*)d_in[11];
    const float* a_dst2 = (const float*)d_in[12];
    const float* b2     = (const float*)d_in[13];
    float* out = (float*)d_out;

    float *hx, *f1, *f2, *als, *ald;
    cudaGetSymbolAddress((void**)&hx,  g_hx);
    cudaGetSymbolAddress((void**)&f1,  g_f1);
    cudaGetSymbolAddress((void**)&f2,  g_f2);
    cudaGetSymbolAddress((void**)&als, g_als);
    cudaGetSymbolAddress((void**)&ald, g_ald);
    __nv_bfloat16 *w0hi, *w0lo, *w1hi, *w1lo, *w2hi, *w2lo;
    cudaGetSymbolAddress((void**)&w0hi, g_w0hi);
    cudaGetSymbolAddress((void**)&w0lo, g_w0lo);
    cudaGetSymbolAddress((void**)&w1hi, g_w1hi);
    cudaGetSymbolAddress((void**)&w1lo, g_w1lo);
    cudaGetSymbolAddress((void**)&w2hi, g_w2hi);
    cudaGetSymbolAddress((void**)&w2lo, g_w2lo);

    // [0] weight splits
    split_weights_kernel<<<(W0N + W1N + W2N + 255) / 256, 256>>>(W0, W1, W2);
    // [1..2] CSR build part 1
    zero_deg_kernel<<<(NNODES + 255) / 256, 256>>>();
    count_kernel<<<(NETOT + 255) / 256, 256>>>(ei);
    // [3] gemm layer0 — positioned so ncu (-s 5 -c 1) profiles it
    {
        dim3 grid((NNODES + 127) / 128, 8);
        gemm_mma3_kernel<<<grid, 256>>>(x, w0hi, w0lo, hx, NNODES, 256, 512);
    }
    // [4..5] CSR build part 2
    scan_kernel<<<1, 1024>>>();
    scatter_kernel<<<(NETOT + 255) / 256, 256>>>(ei);

    // ---- layer 0 rest
    logits_kernel<<<NNODES, 256>>>(hx, a_src0, a_dst0, als, ald, 8, 64);
    aggregate_kernel<<<NNODES, 256>>>(hx, als, ald, b0, f1, 8, 64, 1);
    // ---- layer 1
    {
        dim3 grid((NNODES + 127) / 128, 8);
        gemm_mma3_kernel<<<grid, 256>>>(f1, w1hi, w1lo, hx, NNODES, 512, 512);
        logits_kernel<<<NNODES, 256>>>(hx, a_src1, a_dst1, als, ald, 8, 64);
        aggregate_kernel<<<NNODES, 256>>>(hx, als, ald, b1, f2, 8, 64, 1);
    }
    // ---- layer 2
    {
        dim3 grid((NNODES + 127) / 128, 1);
        gemm_mma3_kernel<<<grid, 256>>>(f2, w2hi, w2lo, hx, NNODES, 512, 40);
        logits_kernel<<<NNODES, 32>>>(hx, a_src2, a_dst2, als, ald, 1, 40);
        aggregate_kernel<<<NNODES, 256>>>(hx, als, ald, b2, out, 1, 40, 0);
    }
    (void)in_sizes; (void)n_in; (void)out_size;
}

// round 15
// speedup vs baseline: 2.4833x; 1.0831x over previous
#include <cuda_runtime.h>
#include <cuda_bf16.h>
#include <cstdint>
#include <cstddef>

#define NNODES   10000
#define NEDGES   160000
#define NETOT    170000   // + self loops
#define HMAX     8

// ---------------- scratch (device globals; no allocation allowed) ----------
__device__ float g_hx [NNODES * 512];
__device__ float g_f1 [NNODES * 512];
__device__ float g_f2 [NNODES * 512];
__device__ float g_als[NNODES * HMAX];
__device__ float g_ald[NNODES * HMAX];
__device__ int   g_deg[NNODES];
__device__ int   g_off[NNODES + 1];
__device__ int   g_cur[NNODES];
__device__ int   g_csr_src[NETOT];

// bf16 split weight buffers
__device__ __nv_bfloat16 g_w0hi[256 * 512], g_w0lo[256 * 512];
__device__ __nv_bfloat16 g_w1hi[512 * 512], g_w1lo[512 * 512];
__device__ __nv_bfloat16 g_w2hi[512 * 40],  g_w2lo[512 * 40];

#define W0N (256 * 512)
#define W1N (512 * 512)
#define W2N (512 * 40)

// ---------------- combined weight split + deg zero (one launch) -------------
__global__ void split_weights_kernel(const float* __restrict__ W0,
                                     const float* __restrict__ W1,
                                     const float* __restrict__ W2)
{
    int i = blockIdx.x * blockDim.x + threadIdx.x;
    if (i < NNODES) g_deg[i] = 0;
    const float* src;
    __nv_bfloat16 *hi, *lo;
    int j;
    if (i < W0N)                   { src = W0; hi = g_w0hi; lo = g_w0lo; j = i; }
    else if (i < W0N + W1N)        { src = W1; hi = g_w1hi; lo = g_w1lo; j = i - W0N; }
    else if (i < W0N + W1N + W2N)  { src = W2; hi = g_w2hi; lo = g_w2lo; j = i - W0N - W1N; }
    else return;
    float x = src[j];
    __nv_bfloat16 h = __float2bfloat16_rn(x);
    hi[j] = h;
    lo[j] = __float2bfloat16_rn(x - __bfloat162float(h));
}

// ---------------- CSR build ------------------------------------------------
__global__ void count_kernel(const int* __restrict__ ei) {
    int i = blockIdx.x * blockDim.x + threadIdx.x;
    if (i >= NETOT) return;
    int dst = (i < NEDGES) ? ei[NEDGES + i] : (i - NEDGES);
    atomicAdd(&g_deg[dst], 1);
}

// single block, 1024 threads, shfl-based scan (2 barriers)
__global__ void scan_kernel() {
    const int SEG = 10;   // 1024*10 >= NNODES
    int tid  = threadIdx.x;
    int lane = tid & 31;
    int warp = tid >> 5;
    int beg  = tid * SEG;
    int end  = beg + SEG; if (end > NNODES) end = NNODES;
    int local[SEG];
    int s = 0;
    for (int i = beg; i < end; i++) { int d = g_deg[i]; local[i - beg] = d; s += d; }
    // warp inclusive scan
    int incl = s;
#pragma unroll
    for (int d = 1; d < 32; d <<= 1) {
        int v = __shfl_up_sync(0xffffffffu, incl, d);
        if (lane >= d) incl += v;
    }
    __shared__ int wsum[32];
    if (lane == 31) wsum[warp] = incl;
    __syncthreads();
    if (warp == 0) {
        int v = wsum[lane];
        int iv = v;
#pragma unroll
        for (int d = 1; d < 32; d <<= 1) {
            int t = __shfl_up_sync(0xffffffffu, iv, d);
            if (lane >= d) iv += t;
        }
        wsum[lane] = iv;
    }
    __syncthreads();
    int run = (warp > 0 ? wsum[warp - 1] : 0) + (incl - s);
    for (int i = beg; i < end; i++) {
        g_off[i] = run;
        g_cur[i] = run;
        run += local[i - beg];
    }
    if (tid == 1023) g_off[NNODES] = wsum[31];
}

__global__ void scatter_kernel(const int* __restrict__ ei) {
    int i = blockIdx.x * blockDim.x + threadIdx.x;
    if (i >= NETOT) return;
    int src, dst;
    if (i < NEDGES) { src = ei[i]; dst = ei[NEDGES + i]; }
    else            { src = i - NEDGES; dst = src; }
    int p = atomicAdd(&g_cur[dst], 1);
    g_csr_src[p] = src;
}

// ---------------- tensor-core GEMM + fused attention logits -----------------
// C = Ahi@Bhi + Ahi@Blo + Alo@Bhi ; A fp32 [M,K] split in-kernel.
// Block tile 128x64 (col tile == C), so blockIdx.y == head.
// Epilogue also computes als/ald = <hx_row, a_src/a_dst> for this head.
#define RS  40
#define RSB 72

__device__ __forceinline__ void mma16816(float* c, const uint32_t* a, const uint32_t* b)
{
    asm volatile(
        "mma.sync.aligned.m16n8k16.row.col.f32.bf16.bf16.f32 "
        "{%0,%1,%2,%3}, {%4,%5,%6,%7}, {%8,%9}, {%0,%1,%2,%3};\n"
        : "+f"(c[0]), "+f"(c[1]), "+f"(c[2]), "+f"(c[3])
        : "r"(a[0]), "r"(a[1]), "r"(a[2]), "r"(a[3]), "r"(b[0]), "r"(b[1]));
}

__device__ __forceinline__ void ldsm4(uint32_t* r, uint32_t addr)
{
    asm volatile("ldmatrix.sync.aligned.m8n8.x4.shared.b16 {%0,%1,%2,%3}, [%4];"
        : "=r"(r[0]), "=r"(r[1]), "=r"(r[2]), "=r"(r[3]) : "r"(addr));
}

__device__ __forceinline__ void ldsm4t(uint32_t* r, uint32_t addr)
{
    asm volatile("ldmatrix.sync.aligned.m8n8.x4.trans.shared.b16 {%0,%1,%2,%3}, [%4];"
        : "=r"(r[0]), "=r"(r[1]), "=r"(r[2]), "=r"(r[3]) : "r"(addr));
}

__global__ __launch_bounds__(256, 2) void gemm_mma3_kernel(
    const float* __restrict__ A,
    const __nv_bfloat16* __restrict__ Bhi, const __nv_bfloat16* __restrict__ Blo,
    float* __restrict__ C, int M, int K, int Ncol,
    const float* __restrict__ a_src, const float* __restrict__ a_dst,
    float* __restrict__ als, float* __restrict__ ald, int H, int Cc)
{
    __shared__ __align__(16) __nv_bfloat16 Ash[128 * RS];
    __shared__ __align__(16) __nv_bfloat16 Asl[128 * RS];
    __shared__ __align__(16) __nv_bfloat16 Bsh[32 * RSB];
    __shared__ __align__(16) __nv_bfloat16 Bsl[32 * RSB];
    __shared__ float s_ls[128], s_ld[128];

    int tid  = threadIdx.x;
    int wid  = tid >> 5;
    int lane = tid & 31;
    int g    = lane >> 2;
    int tig  = lane & 3;
    int wm   = wid & 3;
    int wn   = wid >> 2;
    int wrow = wm * 32;
    int wcol = wn * 32;
    int row0 = blockIdx.x * 128;
    int col0 = blockIdx.y * 64;
    int head = blockIdx.y;           // col tile 64 == C (layer2: y=0, H=1)

    int a_row[4], a_col[4];
#pragma unroll
    for (int i = 0; i < 4; i++) {
        int e = tid + i * 256;
        a_row[i] = e >> 3;
        a_col[i] = (e & 7) * 4;
    }
    int b_kk[2], b_nn[2];
#pragma unroll
    for (int i = 0; i < 2; i++) {
        int e = tid + i * 256;
        b_kk[i] = e >> 4;
        b_nn[i] = (e & 15) * 4;
    }

    int q   = lane >> 3;
    int iL  = lane & 7;
    int roff = ((q & 1) ? 8 : 0) + iL;
    int soff = (q >> 1) ? 8 : 0;
    uint32_t ashL = (uint32_t)__cvta_generic_to_shared(Ash) + ((wrow + roff) * RS + soff) * 2;
    uint32_t aslL = (uint32_t)__cvta_generic_to_shared(Asl) + ((wrow + roff) * RS + soff) * 2;
    uint32_t bshL = (uint32_t)__cvta_generic_to_shared(Bsh) + (roff * RSB + wcol + soff) * 2;
    uint32_t bslL = (uint32_t)__cvta_generic_to_shared(Bsl) + (roff * RSB + wcol + soff) * 2;

    float acc[2][4][4];
#pragma unroll
    for (int i = 0; i < 2; i++)
#pragma unroll
        for (int j = 0; j < 4; j++)
#pragma unroll
            for (int p = 0; p < 4; p++) acc[i][j][p] = 0.f;

    float4 pa[4];
    uint2  pbh[2], pbl[2];

#pragma unroll
    for (int i = 0; i < 4; i++) {
        pa[i] = make_float4(0.f, 0.f, 0.f, 0.f);
        int gr = row0 + a_row[i];
        if (gr < M) pa[i] = *(const float4*)(A + (size_t)gr * K + a_col[i]);
    }
#pragma unroll
    for (int i = 0; i < 2; i++) {
        pbh[i] = make_uint2(0u, 0u); pbl[i] = make_uint2(0u, 0u);
        if (col0 + b_nn[i] < Ncol) {
            size_t off = (size_t)b_kk[i] * Ncol + col0 + b_nn[i];
            pbh[i] = *(const uint2*)(Bhi + off);
            pbl[i] = *(const uint2*)(Blo + off);
        }
    }

#pragma unroll 1
    for (int k0 = 0; k0 < K; k0 += 32) {
#pragma unroll
        for (int i = 0; i < 4; i++) {
            float f[4] = {pa[i].x, pa[i].y, pa[i].z, pa[i].w};
            __nv_bfloat16 h[4], l[4];
#pragma unroll
            for (int p = 0; p < 4; p++) {
                h[p] = __float2bfloat16_rn(f[p]);
                l[p] = __float2bfloat16_rn(f[p] - __bfloat162float(h[p]));
            }
            *(uint2*)&Ash[a_row[i] * RS + a_col[i]] = *(uint2*)h;
            *(uint2*)&Asl[a_row[i] * RS + a_col[i]] = *(uint2*)l;
        }
#pragma unroll
        for (int i = 0; i < 2; i++) {
            *(uint2*)&Bsh[b_kk[i] * RSB + b_nn[i]] = pbh[i];
            *(uint2*)&Bsl[b_kk[i] * RSB + b_nn[i]] = pbl[i];
        }
        __syncthreads();

        if (k0 + 32 < K) {
#pragma unroll
            for (int i = 0; i < 4; i++) {
                pa[i] = make_float4(0.f, 0.f, 0.f, 0.f);
                int gr = row0 + a_row[i];
                if (gr < M) pa[i] = *(const float4*)(A + (size_t)gr * K + k0 + 32 + a_col[i]);
            }
#pragma unroll
            for (int i = 0; i < 2; i++) {
                pbh[i] = make_uint2(0u, 0u); pbl[i] = make_uint2(0u, 0u);
                if (col0 + b_nn[i] < Ncol) {
                    size_t off = (size_t)(k0 + 32 + b_kk[i]) * Ncol + col0 + b_nn[i];
                    pbh[i] = *(const uint2*)(Bhi + off);
                    pbl[i] = *(const uint2*)(Blo + off);
                }
            }
        }

#pragma unroll
        for (int kk16 = 0; kk16 < 2; kk16++) {
            uint32_t ah[2][4], al_[2][4];
#pragma unroll
            for (int ma = 0; ma < 2; ma++) {
                uint32_t aoff = ((uint32_t)(ma * 16 * RS + kk16 * 16)) * 2;
                ldsm4(ah[ma],  ashL + aoff);
                ldsm4(al_[ma], aslL + aoff);
            }
            uint32_t bh[2][4], bl[2][4];
#pragma unroll
            for (int p = 0; p < 2; p++) {
                uint32_t boff = ((uint32_t)(kk16 * 16 * RSB + p * 16)) * 2;
                ldsm4t(bh[p], bshL + boff);
                ldsm4t(bl[p], bslL + boff);
            }
#pragma unroll
            for (int na = 0; na < 4; na++) {
                const uint32_t* bph = &bh[na >> 1][(na & 1) * 2];
                const uint32_t* bpl = &bl[na >> 1][(na & 1) * 2];
#pragma unroll
                for (int ma = 0; ma < 2; ma++) {
                    mma16816(acc[ma][na], ah[ma],  bph);
                    mma16816(acc[ma][na], ah[ma],  bpl);
                    mma16816(acc[ma][na], al_[ma], bph);
                }
            }
        }
        __syncthreads();
    }

    // ---- epilogue: write hx tile + fused logits for this head
    // load attention vector channels for this thread's 8 columns
    float asv[4][2], adv[4][2];
#pragma unroll
    for (int na = 0; na < 4; na++) {
        int ch = wcol + na * 8 + tig * 2;
        asv[na][0] = (ch     < Cc) ? a_src[head * Cc + ch]     : 0.f;
        asv[na][1] = (ch + 1 < Cc) ? a_src[head * Cc + ch + 1] : 0.f;
        adv[na][0] = (ch     < Cc) ? a_dst[head * Cc + ch]     : 0.f;
        adv[na][1] = (ch + 1 < Cc) ? a_dst[head * Cc + ch + 1] : 0.f;
    }

#pragma unroll
    for (int ma = 0; ma < 2; ma++) {
        float ssA = 0.f, sdA = 0.f, ssB = 0.f, sdB = 0.f;
#pragma unroll
        for (int na = 0; na < 4; na++) {
            int r = row0 + wrow + ma * 16 + g;
            int c = col0 + wcol + na * 8 + tig * 2;
            if (c < Ncol) {
                if (r < M)
                    *(float2*)&C[(size_t)r * Ncol + c] =
                        make_float2(acc[ma][na][0], acc[ma][na][1]);
                if (r + 8 < M)
                    *(float2*)&C[(size_t)(r + 8) * Ncol + c] =
                        make_float2(acc[ma][na][2], acc[ma][na][3]);
            }
            ssA += acc[ma][na][0] * asv[na][0] + acc[ma][na][1] * asv[na][1];
            sdA += acc[ma][na][0] * adv[na][0] + acc[ma][na][1] * adv[na][1];
            ssB += acc[ma][na][2] * asv[na][0] + acc[ma][na][3] * asv[na][1];
            sdB += acc[ma][na][2] * adv[na][0] + acc[ma][na][3] * adv[na][1];
        }
        // reduce over tig (lanes g*4 + tig)
#pragma unroll
        for (int d = 1; d < 4; d <<= 1) {
            ssA += __shfl_xor_sync(0xffffffffu, ssA, d);
            sdA += __shfl_xor_sync(0xffffffffu, sdA, d);
            ssB += __shfl_xor_sync(0xffffffffu, ssB, d);
            sdB += __shfl_xor_sync(0xffffffffu, sdB, d);
        }
        int rA = wrow + ma * 16 + g;
        if (wn == 0 && tig == 0) {
            s_ls[rA] = ssA; s_ld[rA] = sdA;
            s_ls[rA + 8] = ssB; s_ld[rA + 8] = sdB;
        }
        __syncthreads();
        if (wn == 1 && tig == 0) {
            int gr = row0 + rA;
            if (gr < M) {
                als[(size_t)gr * H + head] = s_ls[rA] + ssA;
                ald[(size_t)gr * H + head] = s_ld[rA] + sdA;
            }
            if (gr + 8 < M) {
                als[(size_t)(gr + 8) * H + head] = s_ls[rA + 8] + ssB;
                ald[(size_t)(gr + 8) * H + head] = s_ld[rA + 8] + sdB;
            }
        }
        __syncthreads();
    }
}

// ---------------- per-dst softmax + aggregation (single pass) ---------------
__global__ __launch_bounds__(256) void aggregate_kernel(
    const float* __restrict__ hx,
    const float* __restrict__ als, const float* __restrict__ ald,
    const float* __restrict__ bias, float* __restrict__ out,
    int H, int C, int act)
{
    int n   = blockIdx.x;
    int HC  = H * C;
    int tid = threadIdx.x;
    int h   = tid % H;
    int w   = tid / H;
    int NW  = 256 / H;

    __shared__ float sm_ald[HMAX];
    __shared__ float sm_ex[256];
    __shared__ float scratch[256];
    __shared__ int   sm_src[256];

    int e0  = g_off[n];
    int deg = g_off[n + 1] - e0;

    if (tid < H) sm_ald[tid] = ald[(size_t)n * H + tid];
    __syncthreads();
    float myald = sm_ald[h];

    float acc0 = 0.f, acc1 = 0.f, psum = 0.f;
    int c0 = tid, c1 = tid + 256;
    int h0 = (c0 < HC) ? (c0 / C) : 0;
    int h1 = (c1 < HC) ? (c1 / C) : 0;

    for (int base = 0; base < deg; base += NW) {
        int j = base + w;
        if (j < deg) {
            int s = g_csr_src[e0 + j];
            if (h == 0) sm_src[w] = s;
            float v = als[(size_t)s * H + h] + myald;
            v = (v >= 0.f) ? v : 0.2f * v;
            float ex = expf(v);
            sm_ex[w * H + h] = ex;
            psum += ex;
        }
        __syncthreads();
        int lim = deg - base; if (lim > NW) lim = NW;
        int j2 = 0;
        for (; j2 + 1 < lim; j2 += 2) {
            int s0 = sm_src[j2], s1 = sm_src[j2 + 1];
            const float* r0 = hx + (size_t)s0 * HC;
            const float* r1 = hx + (size_t)s1 * HC;
            float a00 = sm_ex[j2 * H + h0], a01 = sm_ex[(j2 + 1) * H + h0];
            float a10 = sm_ex[j2 * H + h1], a11 = sm_ex[(j2 + 1) * H + h1];
            if (c0 < HC) acc0 += r0[c0] * a00 + r1[c0] * a01;
            if (c1 < HC) acc1 += r0[c1] * a10 + r1[c1] * a11;
        }
        if (j2 < lim) {
            int s = sm_src[j2];
            const float* hrow = hx + (size_t)s * HC;
            float a0 = sm_ex[j2 * H + h0];
            float a1 = sm_ex[j2 * H + h1];
            if (c0 < HC) acc0 += hrow[c0] * a0;
            if (c1 < HC) acc1 += hrow[c1] * a1;
        }
        __syncthreads();
    }

    scratch[tid] = psum;
    __syncthreads();
    for (int st = NW >> 1; st > 0; st >>= 1) {
        if (w < st) scratch[tid] += scratch[tid + st * H];
        __syncthreads();
    }
    float d0 = scratch[h0] + 1e-16f;
    float d1 = scratch[h1] + 1e-16f;

    if (c0 < HC) {
        float o = acc0 / d0 + bias[c0];
        if (act) o = (o > 0.f) ? o : expm1f(o);
        out[(size_t)n * HC + c0] = o;
    }
    if (c1 < HC) {
        float o = acc1 / d1 + bias[c1];
        if (act) o = (o > 0.f) ? o : expm1f(o);
        out[(size_t)n * HC + c1] = o;
    }
}

// ---------------- host -----------------------------------------------------
extern "C" void kernel_launch(void* const* d_in, const int* in_sizes, int n_in,
                              void* d_out, int out_size)
{
    const float* x      = (const float*)d_in[0];
    const int*   ei     = (const int*)  d_in[1];
    const float* W0     = (const float*)d_in[2];
    const float* a_src0 = (const float*)d_in[3];
    const float* a_dst0 = (const float*)d_in[4];
    const float* b0     = (const float*)d_in[5];
    const float* W1     = (const float*)d_in[6];
    const float* a_src1 = (const float*)d_in[7];
    const float* a_dst1 = (const float*)d_in[8];
    const float* b1     = (const float*)d_in[9];
    const float* W2     = (const float*)d_in[10];
    const float* a_src2 = (const float*)d_in[11];
    const float* a_dst2 = (const float*)d_in[12];
    const float* b2     = (const float*)d_in[13];
    float* out = (float*)d_out;

    float *hx, *f1, *f2, *als, *ald;
    cudaGetSymbolAddress((void**)&hx,  g_hx);
    cudaGetSymbolAddress((void**)&f1,  g_f1);
    cudaGetSymbolAddress((void**)&f2,  g_f2);
    cudaGetSymbolAddress((void**)&als, g_als);
    cudaGetSymbolAddress((void**)&ald, g_ald);
    __nv_bfloat16 *w0hi, *w0lo, *w1hi, *w1lo, *w2hi, *w2lo;
    cudaGetSymbolAddress((void**)&w0hi, g_w0hi);
    cudaGetSymbolAddress((void**)&w0lo, g_w0lo);
    cudaGetSymbolAddress((void**)&w1hi, g_w1hi);
    cudaGetSymbolAddress((void**)&w1lo, g_w1lo);
    cudaGetSymbolAddress((void**)&w2hi, g_w2hi);
    cudaGetSymbolAddress((void**)&w2lo, g_w2lo);

    // [0] weight splits + deg zero
    split_weights_kernel<<<(W0N + W1N + W2N + 255) / 256, 256>>>(W0, W1, W2);
    // [1] count
    count_kernel<<<(NETOT + 255) / 256, 256>>>(ei);
    // [2] scan
    scan_kernel<<<1, 1024>>>();
    // [3] gemm layer0 (+fused logits) — ncu profiles this slot
    {
        dim3 grid((NNODES + 127) / 128, 8);
        gemm_mma3_kernel<<<grid, 256>>>(x, w0hi, w0lo, hx, NNODES, 256, 512,
                                        a_src0, a_dst0, als, ald, 8, 64);
    }
    // [4] scatter
    scatter_kernel<<<(NETOT + 255) / 256, 256>>>(ei);

    // layer 0 aggregate
    aggregate_kernel<<<NNODES, 256>>>(hx, als, ald, b0, f1, 8, 64, 1);
    // ---- layer 1
    {
        dim3 grid((NNODES + 127) / 128, 8);
        gemm_mma3_kernel<<<grid, 256>>>(f1, w1hi, w1lo, hx, NNODES, 512, 512,
                                        a_src1, a_dst1, als, ald, 8, 64);
        aggregate_kernel<<<NNODES, 256>>>(hx, als, ald, b1, f2, 8, 64, 1);
    }
    // ---- layer 2
    {
        dim3 grid((NNODES + 127) / 128, 1);
        gemm_mma3_kernel<<<grid, 256>>>(f2, w2hi, w2lo, hx, NNODES, 512, 40,
                                        a_src2, a_dst2, als, ald, 1, 40);
        aggregate_kernel<<<NNODES, 256>>>(hx, als, ald, b2, out, 1, 40, 0);
    }
    (void)in_sizes; (void)n_in; (void)out_size;
}

// round 16
// speedup vs baseline: 2.6986x; 1.0867x over previous
#include <cuda_runtime.h>
#include <cuda_bf16.h>
#include <cstdint>
#include <cstddef>

#define NNODES   10000
#define NEDGES   160000
#define NETOT    170000   // + self loops
#define HMAX     8

// ---------------- scratch (device globals; no allocation allowed) ----------
__device__ float g_hx [NNODES * 512];
__device__ float g_f1 [NNODES * 512];
__device__ float g_f2 [NNODES * 512];
__device__ float g_als[NNODES * HMAX];
__device__ float g_ald[NNODES * HMAX];
__device__ int   g_deg[NNODES];
__device__ int   g_off[NNODES + 1];
__device__ int   g_cur[NNODES];
__device__ int   g_csr_src[NETOT];

// bf16 split weight buffers
__device__ __nv_bfloat16 g_w0hi[256 * 512], g_w0lo[256 * 512];
__device__ __nv_bfloat16 g_w1hi[512 * 512], g_w1lo[512 * 512];
__device__ __nv_bfloat16 g_w2hi[512 * 40],  g_w2lo[512 * 40];

#define W0N (256 * 512)
#define W1N (512 * 512)
#define W2N (512 * 40)

// ---------------- combined weight split + deg zero (one launch) -------------
__global__ void split_weights_kernel(const float* __restrict__ W0,
                                     const float* __restrict__ W1,
                                     const float* __restrict__ W2)
{
    int i = blockIdx.x * blockDim.x + threadIdx.x;
    if (i < NNODES) g_deg[i] = 0;
    const float* src;
    __nv_bfloat16 *hi, *lo;
    int j;
    if (i < W0N)                   { src = W0; hi = g_w0hi; lo = g_w0lo; j = i; }
    else if (i < W0N + W1N)        { src = W1; hi = g_w1hi; lo = g_w1lo; j = i - W0N; }
    else if (i < W0N + W1N + W2N)  { src = W2; hi = g_w2hi; lo = g_w2lo; j = i - W0N - W1N; }
    else return;
    float x = src[j];
    __nv_bfloat16 h = __float2bfloat16_rn(x);
    hi[j] = h;
    lo[j] = __float2bfloat16_rn(x - __bfloat162float(h));
}

// ---------------- CSR build ------------------------------------------------
__global__ void count_kernel(const int* __restrict__ ei) {
    int i = blockIdx.x * blockDim.x + threadIdx.x;
    if (i >= NETOT) return;
    int dst = (i < NEDGES) ? ei[NEDGES + i] : (i - NEDGES);
    atomicAdd(&g_deg[dst], 1);
}

// single block, 1024 threads, shfl-based scan (2 barriers)
__global__ void scan_kernel() {
    const int SEG = 10;
    int tid  = threadIdx.x;
    int lane = tid & 31;
    int warp = tid >> 5;
    int beg  = tid * SEG;
    int end  = beg + SEG; if (end > NNODES) end = NNODES;
    int local[SEG];
    int s = 0;
    for (int i = beg; i < end; i++) { int d = g_deg[i]; local[i - beg] = d; s += d; }
    int incl = s;
#pragma unroll
    for (int d = 1; d < 32; d <<= 1) {
        int v = __shfl_up_sync(0xffffffffu, incl, d);
        if (lane >= d) incl += v;
    }
    __shared__ int wsum[32];
    if (lane == 31) wsum[warp] = incl;
    __syncthreads();
    if (warp == 0) {
        int v = wsum[lane];
        int iv = v;
#pragma unroll
        for (int d = 1; d < 32; d <<= 1) {
            int t = __shfl_up_sync(0xffffffffu, iv, d);
            if (lane >= d) iv += t;
        }
        wsum[lane] = iv;
    }
    __syncthreads();
    int run = (warp > 0 ? wsum[warp - 1] : 0) + (incl - s);
    for (int i = beg; i < end; i++) {
        g_off[i] = run;
        g_cur[i] = run;
        run += local[i - beg];
    }
    if (tid == 1023) g_off[NNODES] = wsum[31];
}

__global__ void scatter_kernel(const int* __restrict__ ei) {
    int i = blockIdx.x * blockDim.x + threadIdx.x;
    if (i >= NETOT) return;
    int src, dst;
    if (i < NEDGES) { src = ei[i]; dst = ei[NEDGES + i]; }
    else            { src = i - NEDGES; dst = src; }
    int p = atomicAdd(&g_cur[dst], 1);
    g_csr_src[p] = src;
}

// ---------------- tensor-core GEMM + fused attention logits -----------------
// C = Ahi@Bhi + Ahi@Blo + Alo@Bhi ; A fp32 [M,K] split in-kernel.
// Block tile 128x64 (col tile == C), so blockIdx.y == head.
// Smem ping-pong double buffering: ONE __syncthreads per k-iter.
#define RS  40
#define RSB 72
#define A_TILE (128 * RS)    // bf16 elements per A buffer
#define B_TILE (32 * RSB)
#define GEMM_SMEM_BYTES (2 * A_TILE * 2 * 2 + 2 * B_TILE * 2 * 2 + 256 * 4)

__device__ __forceinline__ void mma16816(float* c, const uint32_t* a, const uint32_t* b)
{
    asm volatile(
        "mma.sync.aligned.m16n8k16.row.col.f32.bf16.bf16.f32 "
        "{%0,%1,%2,%3}, {%4,%5,%6,%7}, {%8,%9}, {%0,%1,%2,%3};\n"
        : "+f"(c[0]), "+f"(c[1]), "+f"(c[2]), "+f"(c[3])
        : "r"(a[0]), "r"(a[1]), "r"(a[2]), "r"(a[3]), "r"(b[0]), "r"(b[1]));
}

__device__ __forceinline__ void ldsm4(uint32_t* r, uint32_t addr)
{
    asm volatile("ldmatrix.sync.aligned.m8n8.x4.shared.b16 {%0,%1,%2,%3}, [%4];"
        : "=r"(r[0]), "=r"(r[1]), "=r"(r[2]), "=r"(r[3]) : "r"(addr));
}

__device__ __forceinline__ void ldsm4t(uint32_t* r, uint32_t addr)
{
    asm volatile("ldmatrix.sync.aligned.m8n8.x4.trans.shared.b16 {%0,%1,%2,%3}, [%4];"
        : "=r"(r[0]), "=r"(r[1]), "=r"(r[2]), "=r"(r[3]) : "r"(addr));
}

__global__ __launch_bounds__(256, 2) void gemm_mma3_kernel(
    const float* __restrict__ A,
    const __nv_bfloat16* __restrict__ Bhi, const __nv_bfloat16* __restrict__ Blo,
    float* __restrict__ C, int M, int K, int Ncol,
    const float* __restrict__ a_src, const float* __restrict__ a_dst,
    float* __restrict__ als, float* __restrict__ ald, int H, int Cc)
{
    extern __shared__ __align__(16) char smem_raw[];
    __nv_bfloat16* Ash = (__nv_bfloat16*)smem_raw;     // [2][A_TILE]
    __nv_bfloat16* Asl = Ash + 2 * A_TILE;             // [2][A_TILE]
    __nv_bfloat16* Bsh = Asl + 2 * A_TILE;             // [2][B_TILE]
    __nv_bfloat16* Bsl = Bsh + 2 * B_TILE;             // [2][B_TILE]
    float* s_ls = (float*)(Bsl + 2 * B_TILE);
    float* s_ld = s_ls + 128;

    int tid  = threadIdx.x;
    int wid  = tid >> 5;
    int lane = tid & 31;
    int g    = lane >> 2;
    int tig  = lane & 3;
    int wm   = wid & 3;
    int wn   = wid >> 2;
    int wrow = wm * 32;
    int wcol = wn * 32;
    int row0 = blockIdx.x * 128;
    int col0 = blockIdx.y * 64;
    int head = blockIdx.y;

    int a_row[4], a_col[4];
#pragma unroll
    for (int i = 0; i < 4; i++) {
        int e = tid + i * 256;
        a_row[i] = e >> 3;
        a_col[i] = (e & 7) * 4;
    }
    int b_kk[2], b_nn[2];
#pragma unroll
    for (int i = 0; i < 2; i++) {
        int e = tid + i * 256;
        b_kk[i] = e >> 4;
        b_nn[i] = (e & 15) * 4;
    }

    int q   = lane >> 3;
    int iL  = lane & 7;
    int roff = ((q & 1) ? 8 : 0) + iL;
    int soff = (q >> 1) ? 8 : 0;
    uint32_t ashL = (uint32_t)__cvta_generic_to_shared(Ash) + ((wrow + roff) * RS + soff) * 2;
    uint32_t aslL = (uint32_t)__cvta_generic_to_shared(Asl) + ((wrow + roff) * RS + soff) * 2;
    uint32_t bshL = (uint32_t)__cvta_generic_to_shared(Bsh) + (roff * RSB + wcol + soff) * 2;
    uint32_t bslL = (uint32_t)__cvta_generic_to_shared(Bsl) + (roff * RSB + wcol + soff) * 2;

    float acc[2][4][4];
#pragma unroll
    for (int i = 0; i < 2; i++)
#pragma unroll
        for (int j = 0; j < 4; j++)
#pragma unroll
            for (int p = 0; p < 4; p++) acc[i][j][p] = 0.f;

    float4 pa[4];
    uint2  pbh[2], pbl[2];

    // ---- prefetch k0 = 0 into regs
#pragma unroll
    for (int i = 0; i < 4; i++) {
        pa[i] = make_float4(0.f, 0.f, 0.f, 0.f);
        int gr = row0 + a_row[i];
        if (gr < M) pa[i] = *(const float4*)(A + (size_t)gr * K + a_col[i]);
    }
#pragma unroll
    for (int i = 0; i < 2; i++) {
        pbh[i] = make_uint2(0u, 0u); pbl[i] = make_uint2(0u, 0u);
        if (col0 + b_nn[i] < Ncol) {
            size_t off = (size_t)b_kk[i] * Ncol + col0 + b_nn[i];
            pbh[i] = *(const uint2*)(Bhi + off);
            pbl[i] = *(const uint2*)(Blo + off);
        }
    }
    // ---- store k0=0 into buffer 0
#pragma unroll
    for (int i = 0; i < 4; i++) {
        float f[4] = {pa[i].x, pa[i].y, pa[i].z, pa[i].w};
        __nv_bfloat16 h[4], l[4];
#pragma unroll
        for (int p = 0; p < 4; p++) {
            h[p] = __float2bfloat16_rn(f[p]);
            l[p] = __float2bfloat16_rn(f[p] - __bfloat162float(h[p]));
        }
        *(uint2*)&Ash[a_row[i] * RS + a_col[i]] = *(uint2*)h;
        *(uint2*)&Asl[a_row[i] * RS + a_col[i]] = *(uint2*)l;
    }
#pragma unroll
    for (int i = 0; i < 2; i++) {
        *(uint2*)&Bsh[b_kk[i] * RSB + b_nn[i]] = pbh[i];
        *(uint2*)&Bsl[b_kk[i] * RSB + b_nn[i]] = pbl[i];
    }
    __syncthreads();

    int cur = 0;
#pragma unroll 1
    for (int k0 = 0; k0 < K; k0 += 32) {
        bool more = (k0 + 32 < K);
        // ---- issue LDG for next tile
        if (more) {
#pragma unroll
            for (int i = 0; i < 4; i++) {
                pa[i] = make_float4(0.f, 0.f, 0.f, 0.f);
                int gr = row0 + a_row[i];
                if (gr < M) pa[i] = *(const float4*)(A + (size_t)gr * K + k0 + 32 + a_col[i]);
            }
#pragma unroll
            for (int i = 0; i < 2; i++) {
                pbh[i] = make_uint2(0u, 0u); pbl[i] = make_uint2(0u, 0u);
                if (col0 + b_nn[i] < Ncol) {
                    size_t off = (size_t)(k0 + 32 + b_kk[i]) * Ncol + col0 + b_nn[i];
                    pbh[i] = *(const uint2*)(Bhi + off);
                    pbl[i] = *(const uint2*)(Blo + off);
                }
            }
        }

        // ---- compute on buffer `cur`
        uint32_t bufA = (uint32_t)cur * (A_TILE * 2);
        uint32_t bufB = (uint32_t)cur * (B_TILE * 2);
#pragma unroll
        for (int kk16 = 0; kk16 < 2; kk16++) {
            uint32_t ah[2][4], al_[2][4];
#pragma unroll
            for (int ma = 0; ma < 2; ma++) {
                uint32_t aoff = ((uint32_t)(ma * 16 * RS + kk16 * 16)) * 2;
                ldsm4(ah[ma],  ashL + bufA + aoff);
                ldsm4(al_[ma], aslL + bufA + aoff);
            }
            uint32_t bh[2][4], bl[2][4];
#pragma unroll
            for (int p = 0; p < 2; p++) {
                uint32_t boff = ((uint32_t)(kk16 * 16 * RSB + p * 16)) * 2;
                ldsm4t(bh[p], bshL + bufB + boff);
                ldsm4t(bl[p], bslL + bufB + boff);
            }
#pragma unroll
            for (int na = 0; na < 4; na++) {
                const uint32_t* bph = &bh[na >> 1][(na & 1) * 2];
                const uint32_t* bpl = &bl[na >> 1][(na & 1) * 2];
#pragma unroll
                for (int ma = 0; ma < 2; ma++) {
                    mma16816(acc[ma][na], ah[ma],  bph);
                    mma16816(acc[ma][na], ah[ma],  bpl);
                    mma16816(acc[ma][na], al_[ma], bph);
                }
            }
        }

        // ---- store next tile into buffer cur^1 (no conflict with readers)
        if (more) {
            int nxt = cur ^ 1;
            __nv_bfloat16* Ah = Ash + nxt * A_TILE;
            __nv_bfloat16* Al = Asl + nxt * A_TILE;
            __nv_bfloat16* Bh = Bsh + nxt * B_TILE;
            __nv_bfloat16* Bl = Bsl + nxt * B_TILE;
#pragma unroll
            for (int i = 0; i < 4; i++) {
                float f[4] = {pa[i].x, pa[i].y, pa[i].z, pa[i].w};
                __nv_bfloat16 h[4], l[4];
#pragma unroll
                for (int p = 0; p < 4; p++) {
                    h[p] = __float2bfloat16_rn(f[p]);
                    l[p] = __float2bfloat16_rn(f[p] - __bfloat162float(h[p]));
                }
                *(uint2*)&Ah[a_row[i] * RS + a_col[i]] = *(uint2*)h;
                *(uint2*)&Al[a_row[i] * RS + a_col[i]] = *(uint2*)l;
            }
#pragma unroll
            for (int i = 0; i < 2; i++) {
                *(uint2*)&Bh[b_kk[i] * RSB + b_nn[i]] = pbh[i];
                *(uint2*)&Bl[b_kk[i] * RSB + b_nn[i]] = pbl[i];
            }
        }
        __syncthreads();
        cur ^= 1;
    }

    // ---- epilogue: write hx tile + fused logits for this head
    float asv[4][2], adv[4][2];
#pragma unroll
    for (int na = 0; na < 4; na++) {
        int ch = wcol + na * 8 + tig * 2;
        asv[na][0] = (ch     < Cc) ? a_src[head * Cc + ch]     : 0.f;
        asv[na][1] = (ch + 1 < Cc) ? a_src[head * Cc + ch + 1] : 0.f;
        adv[na][0] = (ch     < Cc) ? a_dst[head * Cc + ch]     : 0.f;
        adv[na][1] = (ch + 1 < Cc) ? a_dst[head * Cc + ch + 1] : 0.f;
    }

#pragma unroll
    for (int ma = 0; ma < 2; ma++) {
        float ssA = 0.f, sdA = 0.f, ssB = 0.f, sdB = 0.f;
#pragma unroll
        for (int na = 0; na < 4; na++) {
            int r = row0 + wrow + ma * 16 + g;
            int c = col0 + wcol + na * 8 + tig * 2;
            if (c < Ncol) {
                if (r < M)
                    *(float2*)&C[(size_t)r * Ncol + c] =
                        make_float2(acc[ma][na][0], acc[ma][na][1]);
                if (r + 8 < M)
                    *(float2*)&C[(size_t)(r + 8) * Ncol + c] =
                        make_float2(acc[ma][na][2], acc[ma][na][3]);
            }
            ssA += acc[ma][na][0] * asv[na][0] + acc[ma][na][1] * asv[na][1];
            sdA += acc[ma][na][0] * adv[na][0] + acc[ma][na][1] * adv[na][1];
            ssB += acc[ma][na][2] * asv[na][0] + acc[ma][na][3] * asv[na][1];
            sdB += acc[ma][na][2] * adv[na][0] + acc[ma][na][3] * adv[na][1];
        }
#pragma unroll
        for (int d = 1; d < 4; d <<= 1) {
            ssA += __shfl_xor_sync(0xffffffffu, ssA, d);
            sdA += __shfl_xor_sync(0xffffffffu, sdA, d);
            ssB += __shfl_xor_sync(0xffffffffu, ssB, d);
            sdB += __shfl_xor_sync(0xffffffffu, sdB, d);
        }
        int rA = wrow + ma * 16 + g;
        if (wn == 0 && tig == 0) {
            s_ls[rA] = ssA; s_ld[rA] = sdA;
            s_ls[rA + 8] = ssB; s_ld[rA + 8] = sdB;
        }
        __syncthreads();
        if (wn == 1 && tig == 0) {
            int gr = row0 + rA;
            if (gr < M) {
                als[(size_t)gr * H + head] = s_ls[rA] + ssA;
                ald[(size_t)gr * H + head] = s_ld[rA] + sdA;
            }
            if (gr + 8 < M) {
                als[(size_t)(gr + 8) * H + head] = s_ls[rA + 8] + ssB;
                ald[(size_t)(gr + 8) * H + head] = s_ld[rA + 8] + sdB;
            }
        }
        __syncthreads();
    }
}

// ---------------- per-dst softmax + aggregation (single pass, float2) -------
__global__ __launch_bounds__(256) void aggregate_kernel(
    const float* __restrict__ hx,
    const float* __restrict__ als, const float* __restrict__ ald,
    const float* __restrict__ bias, float* __restrict__ out,
    int H, int C, int act)
{
    int n   = blockIdx.x;
    int HC  = H * C;
    int tid = threadIdx.x;
    int h   = tid % H;
    int w   = tid / H;
    int NW  = 256 / H;

    __shared__ float sm_ald[HMAX];
    __shared__ float sm_ex[256];
    __shared__ float scratch[256];
    __shared__ int   sm_src[256];

    int e0  = g_off[n];
    int deg = g_off[n + 1] - e0;

    if (tid < H) sm_ald[tid] = ald[(size_t)n * H + tid];
    __syncthreads();
    float myald = sm_ald[h];

    int c = tid * 2;                 // contiguous channel pair (never crosses head)
    bool active = (c < HC);
    int ch = active ? (c / C) : 0;

    float accx = 0.f, accy = 0.f, psum = 0.f;

    for (int base = 0; base < deg; base += NW) {
        int j = base + w;
        if (j < deg) {
            int s = g_csr_src[e0 + j];
            if (h == 0) sm_src[w] = s;
            float v = als[(size_t)s * H + h] + myald;
            v = (v >= 0.f) ? v : 0.2f * v;
            float ex = expf(v);
            sm_ex[w * H + h] = ex;
            psum += ex;
        }
        __syncthreads();
        if (active) {
            int lim = deg - base; if (lim > NW) lim = NW;
            int j2 = 0;
            for (; j2 + 3 < lim; j2 += 4) {
                int s0 = sm_src[j2],     s1 = sm_src[j2 + 1];
                int s2 = sm_src[j2 + 2], s3 = sm_src[j2 + 3];
                float2 v0 = *(const float2*)(hx + (size_t)s0 * HC + c);
                float2 v1 = *(const float2*)(hx + (size_t)s1 * HC + c);
                float2 v2 = *(const float2*)(hx + (size_t)s2 * HC + c);
                float2 v3 = *(const float2*)(hx + (size_t)s3 * HC + c);
                float a0 = sm_ex[j2 * H + ch],       a1 = sm_ex[(j2 + 1) * H + ch];
                float a2 = sm_ex[(j2 + 2) * H + ch], a3 = sm_ex[(j2 + 3) * H + ch];
                accx += v0.x * a0 + v1.x * a1 + v2.x * a2 + v3.x * a3;
                accy += v0.y * a0 + v1.y * a1 + v2.y * a2 + v3.y * a3;
            }
            for (; j2 < lim; j2++) {
                int s = sm_src[j2];
                float2 v = *(const float2*)(hx + (size_t)s * HC + c);
                float a = sm_ex[j2 * H + ch];
                accx += v.x * a;
                accy += v.y * a;
            }
        }
        __syncthreads();
    }

    scratch[tid] = psum;
    __syncthreads();
    for (int st = NW >> 1; st > 0; st >>= 1) {
        if (w < st) scratch[tid] += scratch[tid + st * H];
        __syncthreads();
    }

    if (active) {
        float d = scratch[ch] + 1e-16f;
        float ox = accx / d + bias[c];
        float oy = accy / d + bias[c + 1];
        if (act) {
            ox = (ox > 0.f) ? ox : expm1f(ox);
            oy = (oy > 0.f) ? oy : expm1f(oy);
        }
        *(float2*)(out + (size_t)n * HC + c) = make_float2(ox, oy);
    }
}

// ---------------- host -----------------------------------------------------
extern "C" void kernel_launch(void* const* d_in, const int* in_sizes, int n_in,
                              void* d_out, int out_size)
{
    const float* x      = (const float*)d_in[0];
    const int*   ei     = (const int*)  d_in[1];
    const float* W0     = (const float*)d_in[2];
    const float* a_src0 = (const float*)d_in[3];
    const float* a_dst0 = (const float*)d_in[4];
    const float* b0     = (const float*)d_in[5];
    const float* W1     = (const float*)d_in[6];
    const float* a_src1 = (const float*)d_in[7];
    const float* a_dst1 = (const float*)d_in[8];
    const float* b1     = (const float*)d_in[9];
    const float* W2     = (const float*)d_in[10];
    const float* a_src2 = (const float*)d_in[11];
    const float* a_dst2 = (const float*)d_in[12];
    const float* b2     = (const float*)d_in[13];
    float* out = (float*)d_out;

    float *hx, *f1, *f2, *als, *ald;
    cudaGetSymbolAddress((void**)&hx,  g_hx);
    cudaGetSymbolAddress((void**)&f1,  g_f1);
    cudaGetSymbolAddress((void**)&f2,  g_f2);
    cudaGetSymbolAddress((void**)&als, g_als);
    cudaGetSymbolAddress((void**)&ald, g_ald);
    __nv_bfloat16 *w0hi, *w0lo, *w1hi, *w1lo, *w2hi, *w2lo;
    cudaGetSymbolAddress((void**)&w0hi, g_w0hi);
    cudaGetSymbolAddress((void**)&w0lo, g_w0lo);
    cudaGetSymbolAddress((void**)&w1hi, g_w1hi);
    cudaGetSymbolAddress((void**)&w1lo, g_w1lo);
    cudaGetSymbolAddress((void**)&w2hi, g_w2hi);
    cudaGetSymbolAddress((void**)&w2lo, g_w2lo);

    cudaFuncSetAttribute(gemm_mma3_kernel,
                         cudaFuncAttributeMaxDynamicSharedMemorySize,
                         GEMM_SMEM_BYTES);

    // [0] weight splits + deg zero
    split_weights_kernel<<<(W0N + W1N + W2N + 255) / 256, 256>>>(W0, W1, W2);
    // [1] count
    count_kernel<<<(NETOT + 255) / 256, 256>>>(ei);
    // [2] scan
    scan_kernel<<<1, 1024>>>();
    // [3] gemm layer0 (+fused logits) — ncu profiles this slot
    {
        dim3 grid((NNODES + 127) / 128, 8);
        gemm_mma3_kernel<<<grid, 256, GEMM_SMEM_BYTES>>>(
            x, w0hi, w0lo, hx, NNODES, 256, 512,
            a_src0, a_dst0, als, ald, 8, 64);
    }
    // [4] scatter
    scatter_kernel<<<(NETOT + 255) / 256, 256>>>(ei);

    // layer 0 aggregate
    aggregate_kernel<<<NNODES, 256>>>(hx, als, ald, b0, f1, 8, 64, 1);
    // ---- layer 1
    {
        dim3 grid((NNODES + 127) / 128, 8);
        gemm_mma3_kernel<<<grid, 256, GEMM_SMEM_BYTES>>>(
            f1, w1hi, w1lo, hx, NNODES, 512, 512,
            a_src1, a_dst1, als, ald, 8, 64);
        aggregate_kernel<<<NNODES, 256>>>(hx, als, ald, b1, f2, 8, 64, 1);
    }
    // ---- layer 2
    {
        dim3 grid((NNODES + 127) / 128, 1);
        gemm_mma3_kernel<<<grid, 256, GEMM_SMEM_BYTES>>>(
            f2, w2hi, w2lo, hx, NNODES, 512, 40,
            a_src2, a_dst2, als, ald, 1, 40);
        aggregate_kernel<<<NNODES, 256>>>(hx, als, ald, b2, out, 1, 40, 0);
    }
    (void)in_sizes; (void)n_in; (void)out_size;
}